// round 8
// baseline (speedup 1.0000x reference)
#include <cuda_runtime.h>
#include <cuda_bf16.h>
#include <cstdint>
#include <math.h>

#define B_SZ   2
#define SEQ    2048
#define DIM    1024
#define HEADS  16
#define HD     64
#define SCALE  0.125f
#define EXP_C  0.1803368801111243f   /* SCALE * log2(e) */
#define M_TOTAL (B_SZ * SEQ)
#define QKV_N   (3 * DIM)
#define OUT_ELEMS  (B_SZ * SEQ * DIM)
#define BH      (B_SZ * HEADS)
#define PACKED_ELEMS (BH * SEQ * 128)
#define V_ELEMS      (BH * SEQ * HD)

// ---------------- scratch (static device globals) ----------------
__device__ __nv_bfloat16 g_xrh[OUT_ELEMS], g_xrl[OUT_ELEMS];
__device__ __nv_bfloat16 g_xih[OUT_ELEMS], g_xil[OUT_ELEMS];
__device__ __nv_bfloat16 g_wqrh[QKV_N * DIM], g_wqrl[QKV_N * DIM];
__device__ __nv_bfloat16 g_wqih[QKV_N * DIM], g_wqil[QKV_N * DIM];
__device__ __nv_bfloat16 g_worh[DIM * DIM], g_worl[DIM * DIM];
__device__ __nv_bfloat16 g_woih[DIM * DIM], g_woil[DIM * DIM];
__device__ __nv_bfloat16 g_qph[PACKED_ELEMS], g_qpl[PACKED_ELEMS];
__device__ __nv_bfloat16 g_kph[PACKED_ELEMS], g_kpl[PACKED_ELEMS];
__device__ __nv_bfloat16 g_vrh[V_ELEMS], g_vrl[V_ELEMS];
__device__ __nv_bfloat16 g_vih[V_ELEMS], g_vil[V_ELEMS];
__device__ __nv_bfloat16 g_oarh[OUT_ELEMS], g_oarl[OUT_ELEMS];
__device__ __nv_bfloat16 g_oaih[OUT_ELEMS], g_oail[OUT_ELEMS];

// ---------------- helpers ----------------
__device__ __forceinline__ uint32_t smem_u32(const void* p) {
    uint32_t a;
    asm("{ .reg .u64 t; cvta.to.shared.u64 t, %1; cvt.u32.u64 %0, t; }" : "=r"(a) : "l"(p));
    return a;
}
__device__ __forceinline__ void cp_async16(uint32_t dst, const void* src) {
    asm volatile("cp.async.cg.shared.global [%0], [%1], 16;" :: "r"(dst), "l"(src) : "memory");
}
#define CP_COMMIT()  asm volatile("cp.async.commit_group;" ::: "memory")
#define CP_WAIT0()   asm volatile("cp.async.wait_group 0;" ::: "memory")
#define CP_WAIT1()   asm volatile("cp.async.wait_group 1;" ::: "memory")

__device__ __forceinline__ void mma_bf16(float c[4], const uint32_t a[4], const uint32_t b[2]) {
    asm volatile("mma.sync.aligned.m16n8k16.row.col.f32.bf16.bf16.f32 "
                 "{%0,%1,%2,%3}, {%4,%5,%6,%7}, {%8,%9}, {%0,%1,%2,%3};"
                 : "+f"(c[0]), "+f"(c[1]), "+f"(c[2]), "+f"(c[3])
                 : "r"(a[0]), "r"(a[1]), "r"(a[2]), "r"(a[3]), "r"(b[0]), "r"(b[1]));
}
__device__ __forceinline__ void ldsm_x4(uint32_t r[4], uint32_t a) {
    asm volatile("ldmatrix.sync.aligned.m8n8.x4.shared.b16 {%0,%1,%2,%3}, [%4];"
                 : "=r"(r[0]), "=r"(r[1]), "=r"(r[2]), "=r"(r[3]) : "r"(a));
}
__device__ __forceinline__ void ldsm_x2(uint32_t r[2], uint32_t a) {
    asm volatile("ldmatrix.sync.aligned.m8n8.x2.shared.b16 {%0,%1}, [%2];"
                 : "=r"(r[0]), "=r"(r[1]) : "r"(a));
}
__device__ __forceinline__ void ldsm_x2t(uint32_t r[2], uint32_t a) {
    asm volatile("ldmatrix.sync.aligned.m8n8.x2.trans.shared.b16 {%0,%1}, [%2];"
                 : "=r"(r[0]), "=r"(r[1]) : "r"(a));
}
__device__ __forceinline__ uint32_t pack_bf16(float a, float b) {
    uint32_t r;   // low half = a, high half = b
    asm("cvt.rn.bf16x2.f32 %0, %1, %2;" : "=r"(r) : "f"(b), "f"(a));
    return r;
}
__device__ __forceinline__ void split2(float a, float b, uint32_t& hp, uint32_t& lp) {
    hp = pack_bf16(a, b);
    const float va = __uint_as_float(hp << 16);
    const float vb = __uint_as_float(hp & 0xffff0000u);
    lp = pack_bf16(a - va, b - vb);
}
__device__ __forceinline__ float ex2f(float x) {
    float r; asm("ex2.approx.f32 %0, %1;" : "=f"(r) : "f"(x)); return r;
}

// ---------------- fused fp32 -> bf16 hi/lo splits (one launch) ----------------
#define N_X4   1048576      /* OUT_ELEMS / 4      */
#define N_WQ4  786432       /* QKV_N*DIM / 4      */
#define N_WO4  262144       /* DIM*DIM / 4        */
#define SPLIT_TOTAL (2 * N_X4 + 2 * N_WQ4 + 2 * N_WO4)   /* 4,194,304 */

__global__ void split_all(const float* __restrict__ x_r, const float* __restrict__ x_i,
                          const float* __restrict__ wq_r, const float* __restrict__ wq_i,
                          const float* __restrict__ wo_r, const float* __restrict__ wo_i)
{
    for (int i = blockIdx.x * blockDim.x + threadIdx.x; i < SPLIT_TOTAL;
         i += gridDim.x * blockDim.x) {
        const float* src; __nv_bfloat16 *hi, *lo; int off;
        if (i < 2 * N_X4) {
            if (i < N_X4) { src = x_r; hi = g_xrh; lo = g_xrl; off = i; }
            else          { src = x_i; hi = g_xih; lo = g_xil; off = i - N_X4; }
        } else if (i < 2 * N_X4 + 2 * N_WQ4) {
            const int k = i - 2 * N_X4;
            if (k < N_WQ4) { src = wq_r; hi = g_wqrh; lo = g_wqrl; off = k; }
            else           { src = wq_i; hi = g_wqih; lo = g_wqil; off = k - N_WQ4; }
        } else {
            const int k = i - 2 * N_X4 - 2 * N_WQ4;
            if (k < N_WO4) { src = wo_r; hi = g_worh; lo = g_worl; off = k; }
            else           { src = wo_i; hi = g_woih; lo = g_woil; off = k - N_WO4; }
        }
        float4 v = ((const float4*)src)[off];
        uint2 hp, lp;
        split2(v.x, v.y, hp.x, lp.x);
        split2(v.z, v.w, hp.y, lp.y);
        ((uint2*)hi)[off] = hp;
        ((uint2*)lo)[off] = lp;
    }
}

// ============================================================
// HMMA bf16x3 GEMM, 256x128 CTA tile, 256 threads, 1 CTA/SM.
// blockIdx.z selects real/imag operand set (wave packing).
// QKV=1: scatter epilogue into packed attention buffers.
// QKV=0: plain fp32 output rows.
// ============================================================
#define A_TILE_B 20480                /* 256 rows x 80 B  */
#define B_TILE_B 10240                /* 128 rows x 80 B  */
#define STG_B    61440                /* Ah, Al, Bh, Bl   */
#define GEMM_SMEM (2 * STG_B)         /* 122880           */
#define NCHUNK 32

template<int QKV>
__global__ __launch_bounds__(256, 1)
void gemm_big(const float* __restrict__ bias_r, const float* __restrict__ bias_i,
              float* __restrict__ Yr, float* __restrict__ Yi)
{
    extern __shared__ char smc[];
    const uint32_t sb = smem_u32(smc);
    const int tid = threadIdx.x;
    const int wid = tid >> 5, lid = tid & 31;
    const int wm = wid >> 1, wn = wid & 1;       // 4 x 2 warp grid
    const int g = lid >> 2, tig = lid & 3;
    const int n0 = blockIdx.x * 128;
    const int m0 = blockIdx.y * 256;
    const int z  = blockIdx.z;

    const __nv_bfloat16 *Ah, *Al, *Bhp, *Blp;
    const float* bias;
    if (QKV) {
        if (z == 0) { Ah = g_xrh; Al = g_xrl; Bhp = g_wqrh; Blp = g_wqrl; bias = bias_r; }
        else        { Ah = g_xih; Al = g_xil; Bhp = g_wqih; Blp = g_wqil; bias = bias_i; }
    } else {
        if (z == 0) { Ah = g_oarh; Al = g_oarl; Bhp = g_worh; Blp = g_worl; bias = bias_r; }
        else        { Ah = g_oaih; Al = g_oail; Bhp = g_woih; Blp = g_woil; bias = bias_i; }
    }
    float* Y = (z == 0) ? Yr : Yi;

    auto issue_cp = [&](int chunk, int s) {
        const int k0 = chunk * 32;
        const uint32_t base = sb + (uint32_t)s * STG_B;
#pragma unroll
        for (int i = 0; i < 12; ++i) {
            const int lin = tid + i * 256;           // 0..3071
            if (lin < 2048) {                        // A region
                const int hl = lin >> 10, rc = lin & 1023;
                const int row = rc >> 2, c = rc & 3;
                cp_async16(base + hl * A_TILE_B + row * 80 + c * 16,
                           (hl ? Al : Ah) + (size_t)(m0 + row) * DIM + k0 + c * 8);
            } else {                                 // B region
                const int l2 = lin - 2048;
                const int hl = l2 >> 9, rc = l2 & 511;
                const int row = rc >> 2, c = rc & 3;
                cp_async16(base + 2 * A_TILE_B + hl * B_TILE_B + row * 80 + c * 16,
                           (hl ? Blp : Bhp) + (size_t)(n0 + row) * DIM + k0 + c * 8);
            }
        }
    };

    // ldmatrix lane addresses (relative to stage base)
    const uint32_t a_rel = (uint32_t)((wm * 64 + (lid & 15)) * 80 + ((lid >> 4) << 4));
    const uint32_t b_rel = (uint32_t)((wn * 64 + (lid & 7) + ((lid & 16) >> 1)) * 80 +
                                      ((lid & 8) << 1));

    float acc[4][8][4];
#pragma unroll
    for (int a = 0; a < 4; a++)
#pragma unroll
        for (int b = 0; b < 8; b++)
#pragma unroll
            for (int c = 0; c < 4; c++) acc[a][b][c] = 0.f;

    issue_cp(0, 0);
    CP_COMMIT();

    for (int j = 0; j < NCHUNK; ++j) {
        if (j + 1 < NCHUNK) {
            issue_cp(j + 1, (j + 1) & 1);
            CP_COMMIT();
            CP_WAIT1();
        } else {
            CP_WAIT0();
        }
        __syncthreads();

        const uint32_t st  = sb + (uint32_t)(j & 1) * STG_B;
        const uint32_t aAh = st + a_rel;
        const uint32_t aAl = aAh + A_TILE_B;
        const uint32_t aBh = st + 2 * A_TILE_B + b_rel;
        const uint32_t aBl = aBh + B_TILE_B;

#pragma unroll
        for (int ks = 0; ks < 2; ++ks) {
            uint32_t bh_[4][4], bl_[4][4];
#pragma unroll
            for (int nb2 = 0; nb2 < 4; ++nb2) {
                ldsm_x4(bh_[nb2], aBh + nb2 * 1280 + ks * 32);
                ldsm_x4(bl_[nb2], aBl + nb2 * 1280 + ks * 32);
            }
#pragma unroll
            for (int mi = 0; mi < 4; ++mi) {
                uint32_t ah[4], al[4];
                ldsm_x4(ah, aAh + mi * 1280 + ks * 32);
                ldsm_x4(al, aAl + mi * 1280 + ks * 32);
#pragma unroll
                for (int nb2 = 0; nb2 < 4; ++nb2) {
                    mma_bf16(acc[mi][2 * nb2],     ah, bh_[nb2]);
                    mma_bf16(acc[mi][2 * nb2],     ah, bl_[nb2]);
                    mma_bf16(acc[mi][2 * nb2],     al, bh_[nb2]);
                    mma_bf16(acc[mi][2 * nb2 + 1], ah, bh_[nb2] + 2);
                    mma_bf16(acc[mi][2 * nb2 + 1], ah, bl_[nb2] + 2);
                    mma_bf16(acc[mi][2 * nb2 + 1], al, bh_[nb2] + 2);
                }
            }
        }
        __syncthreads();
    }

    // ---- epilogue ----
#pragma unroll
    for (int nb = 0; nb < 8; ++nb) {
        const int n = n0 + wn * 64 + nb * 8 + tig * 2;
        const float b0v = bias[n], b1v = bias[n + 1];
#pragma unroll
        for (int mi = 0; mi < 4; ++mi) {
            const int mlo = m0 + wm * 64 + mi * 16 + g;
#pragma unroll
            for (int half = 0; half < 2; ++half) {
                const int m = mlo + half * 8;
                const float y0 = acc[mi][nb][half * 2 + 0] + b0v;
                const float y1 = acc[mi][nb][half * 2 + 1] + b1v;
                if (!QKV) {
                    *(float2*)&Y[(size_t)m * DIM + n] = make_float2(y0, y1);
                } else {
                    uint32_t hp, lp;
                    split2(y0, y1, hp, lp);
                    const int which = n >> 10;
                    const int h = (n >> 6) & 15;
                    const int d = n & 63;
                    const int bh = (m >> 11) * HEADS + h;
                    const int ns = m & 2047;
                    if (which == 2) {
                        const size_t idx = ((size_t)bh * SEQ + ns) * HD + d;
                        if (z == 0) {
                            *(uint32_t*)&g_vrh[idx] = hp;
                            *(uint32_t*)&g_vrl[idx] = lp;
                        } else {
                            *(uint32_t*)&g_vih[idx] = hp;
                            *(uint32_t*)&g_vil[idx] = lp;
                        }
                    } else {
                        const size_t idx = ((size_t)bh * SEQ + ns) * 128 + d + (z ? 64 : 0);
                        if (which == 0) {
                            *(uint32_t*)&g_qph[idx] = hp;
                            *(uint32_t*)&g_qpl[idx] = lp;
                        } else {
                            *(uint32_t*)&g_kph[idx] = hp;
                            *(uint32_t*)&g_kpl[idx] = lp;
                        }
                    }
                }
            }
        }
    }
}

// ============================================================
// HMMA flash complex attention (bf16x3), no-max softmax.
// (unchanged from Round 7)
// ============================================================
#define NT 32
#define QSM_H 0u
#define QSM_L 17408u
#define KSM_H 34816u
#define KSM_L 52224u
#define VSM(b) (69632u + (uint32_t)(b) * 9216u)
#define ATT_SMEM 106496

__global__ __launch_bounds__(128, 2)
void attn_mma()
{
    extern __shared__ char smb[];
    const uint32_t sb = smem_u32(smb);
    const int tid = threadIdx.x, w = tid >> 5, L = tid & 31;
    const int bh = blockIdx.y, qt = blockIdx.x;
    const size_t kvrow0 = (size_t)bh * SEQ;

    auto issueQ = [&]() {
        const size_t qb = (kvrow0 + (size_t)qt * 64) * 128;
#pragma unroll
        for (int i = 0; i < 16; ++i) {
            const int lin = tid + i * 128;
            const int hl = lin >> 10, rem = lin & 1023, row = rem >> 4, ch = rem & 15;
            const __nv_bfloat16* src = (hl ? g_qpl : g_qph) + qb + row * 128 + ch * 8;
            cp_async16(sb + (hl ? QSM_L : QSM_H) + row * 272 + ch * 16, src);
        }
    };
    auto issueK = [&](int kt) {
#pragma unroll
        for (int i = 0; i < 16; ++i) {
            const int lin = tid + i * 128;
            const int hl = lin >> 10, rem = lin & 1023, row = rem >> 4, ch = rem & 15;
            const __nv_bfloat16* src = (hl ? g_kpl : g_kph) + (kvrow0 + kt * 64 + row) * 128 + ch * 8;
            cp_async16(sb + (hl ? KSM_L : KSM_H) + row * 272 + ch * 16, src);
        }
    };
    auto issueV = [&](int kt) {
        const __nv_bfloat16* bufs[4] = { g_vrh, g_vrl, g_vih, g_vil };
#pragma unroll
        for (int i = 0; i < 16; ++i) {
            const int lin = tid + i * 128;
            const int bf = lin >> 9, rem = lin & 511, row = rem >> 3, ch = rem & 7;
            cp_async16(sb + VSM(bf) + row * 144 + ch * 16,
                       bufs[bf] + (kvrow0 + kt * 64 + row) * HD + ch * 8);
        }
    };

    float Or[8][4], Oi[8][4];
#pragma unroll
    for (int nb = 0; nb < 8; ++nb)
#pragma unroll
        for (int e = 0; e < 4; ++e) { Or[nb][e] = 0.f; Oi[nb][e] = 0.f; }
    float l0 = 0.f, l1 = 0.f;

    const uint32_t a_off = (uint32_t)((w * 16 + (L & 7) + (L & 8)) * 272 + ((L & 16) ? 16 : 0));
    const uint32_t brow  = (uint32_t)((L & 7) * 272 + ((L & 8) ? 16 : 0));
    const uint32_t vrow  = (uint32_t)(((L & 7) + (L & 8)) * 144);

    issueQ(); issueK(0); CP_COMMIT();
    issueV(0); CP_COMMIT();

    for (int j = 0; j < NT; ++j) {
        CP_WAIT1();
        __syncthreads();

        float Sr[8][4], Si[8][4];
#pragma unroll
        for (int nb = 0; nb < 8; ++nb)
#pragma unroll
            for (int e = 0; e < 4; ++e) { Sr[nb][e] = 0.f; Si[nb][e] = 0.f; }

#pragma unroll
        for (int c = 0; c < 4; ++c) {
            uint32_t fh[4], fl[4], gh[4], gl[4], nh[4], nl[4];
            ldsm_x4(fh, sb + QSM_H + a_off + c * 32);
            ldsm_x4(fl, sb + QSM_L + a_off + c * 32);
            ldsm_x4(gh, sb + QSM_H + a_off + (c + 4) * 32);
            ldsm_x4(gl, sb + QSM_L + a_off + (c + 4) * 32);
#pragma unroll
            for (int r = 0; r < 4; ++r) { nh[r] = fh[r] ^ 0x80008000u; nl[r] = fl[r] ^ 0x80008000u; }
#pragma unroll
            for (int nb = 0; nb < 8; ++nb) {
                const uint32_t ba = (uint32_t)nb * 2176u + brow;
                uint32_t bch[2], bcl[2], bdh[2], bdl[2];
                ldsm_x2(bch, sb + KSM_H + ba + c * 32);
                ldsm_x2(bcl, sb + KSM_L + ba + c * 32);
                ldsm_x2(bdh, sb + KSM_H + ba + (c + 4) * 32);
                ldsm_x2(bdl, sb + KSM_L + ba + (c + 4) * 32);
                mma_bf16(Sr[nb], fh, bch); mma_bf16(Sr[nb], fh, bcl); mma_bf16(Sr[nb], fl, bch);
                mma_bf16(Sr[nb], gh, bdh); mma_bf16(Sr[nb], gh, bdl); mma_bf16(Sr[nb], gl, bdh);
                mma_bf16(Si[nb], gh, bch); mma_bf16(Si[nb], gh, bcl); mma_bf16(Si[nb], gl, bch);
                mma_bf16(Si[nb], nh, bdh); mma_bf16(Si[nb], nh, bdl); mma_bf16(Si[nb], nl, bdh);
            }
        }
        __syncthreads();

        if (j + 1 < NT) { issueK(j + 1); CP_COMMIT(); }

#pragma unroll
        for (int nb = 0; nb < 8; ++nb)
#pragma unroll
            for (int e = 0; e < 4; ++e) {
                const float x = fmaf(Sr[nb][e], Sr[nb][e], Si[nb][e] * Si[nb][e]);
                float rs; asm("rsqrt.approx.f32 %0, %1;" : "=f"(rs) : "f"(x + 1e-30f));
                const float p = ex2f((EXP_C * x) * rs);
                Sr[nb][e] = p;
                if (e < 2) l0 += p; else l1 += p;
            }

        uint32_t Ph[4][4], Pl[4][4];
#pragma unroll
        for (int kc = 0; kc < 4; ++kc) {
            split2(Sr[2 * kc][0],     Sr[2 * kc][1],     Ph[kc][0], Pl[kc][0]);
            split2(Sr[2 * kc][2],     Sr[2 * kc][3],     Ph[kc][1], Pl[kc][1]);
            split2(Sr[2 * kc + 1][0], Sr[2 * kc + 1][1], Ph[kc][2], Pl[kc][2]);
            split2(Sr[2 * kc + 1][2], Sr[2 * kc + 1][3], Ph[kc][3], Pl[kc][3]);
        }

        if (j + 1 < NT) { CP_WAIT1(); } else { CP_WAIT0(); }
        __syncthreads();

#pragma unroll
        for (int kc = 0; kc < 4; ++kc) {
            const uint32_t va = vrow + (uint32_t)kc * 2304u;
#pragma unroll
            for (int nb = 0; nb < 8; ++nb) {
                uint32_t vrh_[2], vrl_[2], vih_[2], vil_[2];
                ldsm_x2t(vrh_, sb + VSM(0) + va + nb * 16);
                ldsm_x2t(vrl_, sb + VSM(1) + va + nb * 16);
                ldsm_x2t(vih_, sb + VSM(2) + va + nb * 16);
                ldsm_x2t(vil_, sb + VSM(3) + va + nb * 16);
                mma_bf16(Or[nb], Ph[kc], vrh_); mma_bf16(Or[nb], Ph[kc], vrl_); mma_bf16(Or[nb], Pl[kc], vrh_);
                mma_bf16(Oi[nb], Ph[kc], vih_); mma_bf16(Oi[nb], Ph[kc], vil_); mma_bf16(Oi[nb], Pl[kc], vih_);
            }
        }
        __syncthreads();

        if (j + 1 < NT) { issueV(j + 1); CP_COMMIT(); }
    }

    l0 += __shfl_xor_sync(0xffffffffu, l0, 1);
    l0 += __shfl_xor_sync(0xffffffffu, l0, 2);
    l1 += __shfl_xor_sync(0xffffffffu, l1, 1);
    l1 += __shfl_xor_sync(0xffffffffu, l1, 2);
    const float inv0 = 1.f / l0, inv1 = 1.f / l1;
    const int b  = bh >> 4;
    const int hh = bh & 15;
    const int r0 = qt * 64 + w * 16 + (L >> 2);
    const size_t base0 = ((size_t)b * SEQ + r0) * DIM + hh * 64;
    const size_t base1 = base0 + (size_t)8 * DIM;
#pragma unroll
    for (int nb = 0; nb < 8; ++nb) {
        const int col = nb * 8 + 2 * (L & 3);
        uint32_t hp, lp;
        split2(Or[nb][0] * inv0, Or[nb][1] * inv0, hp, lp);
        *(uint32_t*)&g_oarh[base0 + col] = hp;  *(uint32_t*)&g_oarl[base0 + col] = lp;
        split2(Oi[nb][0] * inv0, Oi[nb][1] * inv0, hp, lp);
        *(uint32_t*)&g_oaih[base0 + col] = hp;  *(uint32_t*)&g_oail[base0 + col] = lp;
        split2(Or[nb][2] * inv1, Or[nb][3] * inv1, hp, lp);
        *(uint32_t*)&g_oarh[base1 + col] = hp;  *(uint32_t*)&g_oarl[base1 + col] = lp;
        split2(Oi[nb][2] * inv1, Oi[nb][3] * inv1, hp, lp);
        *(uint32_t*)&g_oaih[base1 + col] = hp;  *(uint32_t*)&g_oail[base1 + col] = lp;
    }
}

// ============================================================
extern "C" void kernel_launch(void* const* d_in, const int* in_sizes, int n_in,
                              void* d_out, int out_size)
{
    const float* x_r    = (const float*)d_in[0];
    const float* x_i    = (const float*)d_in[1];
    const float* Wqkv_r = (const float*)d_in[2];
    const float* bqkv_r = (const float*)d_in[3];
    const float* Wqkv_i = (const float*)d_in[4];
    const float* bqkv_i = (const float*)d_in[5];
    const float* Wout_r = (const float*)d_in[6];
    const float* bout_r = (const float*)d_in[7];
    const float* Wout_i = (const float*)d_in[8];
    const float* bout_i = (const float*)d_in[9];

    cudaFuncSetAttribute(gemm_big<1>, cudaFuncAttributeMaxDynamicSharedMemorySize, GEMM_SMEM);
    cudaFuncSetAttribute(gemm_big<0>, cudaFuncAttributeMaxDynamicSharedMemorySize, GEMM_SMEM);
    cudaFuncSetAttribute(attn_mma,    cudaFuncAttributeMaxDynamicSharedMemorySize, ATT_SMEM);

    // 1) fused splits
    split_all<<<2048, 256>>>(x_r, x_i, Wqkv_r, Wqkv_i, Wout_r, Wout_i);

    // 2) QKV projections (real + imag in one launch) -> packed attention inputs
    dim3 gq(QKV_N / 128, M_TOTAL / 256, 2);    // (24, 16, 2)
    gemm_big<1><<<gq, 256, GEMM_SMEM>>>(bqkv_r, bqkv_i, nullptr, nullptr);

    // 3) HMMA flash complex attention
    dim3 ga(SEQ / 64, BH);
    attn_mma<<<ga, 128, ATT_SMEM>>>();

    // 4) output projections (real + imag in one launch) straight into d_out
    float* outr = (float*)d_out;
    float* outi = outr + (size_t)OUT_ELEMS;
    dim3 go(DIM / 128, M_TOTAL / 256, 2);      // (8, 16, 2)
    gemm_big<0><<<go, 256, GEMM_SMEM>>>(bout_r, bout_i, outr, outi);
}

// round 9
// speedup vs baseline: 1.0184x; 1.0184x over previous
#include <cuda_runtime.h>
#include <cuda_bf16.h>
#include <cstdint>
#include <math.h>

#define B_SZ   2
#define SEQ    2048
#define DIM    1024
#define HEADS  16
#define HD     64
#define SCALE  0.125f
#define EXP_C  0.1803368801111243f   /* SCALE * log2(e) */
#define M_TOTAL (B_SZ * SEQ)
#define QKV_N   (3 * DIM)
#define OUT_ELEMS  (B_SZ * SEQ * DIM)
#define BH      (B_SZ * HEADS)
#define PACKED_ELEMS (BH * SEQ * 128)
#define V_ELEMS      (BH * SEQ * HD)

// ---------------- scratch (static device globals) ----------------
__device__ __nv_bfloat16 g_xrh[OUT_ELEMS], g_xrl[OUT_ELEMS];
__device__ __nv_bfloat16 g_xih[OUT_ELEMS], g_xil[OUT_ELEMS];
__device__ __nv_bfloat16 g_wqrh[QKV_N * DIM], g_wqrl[QKV_N * DIM];
__device__ __nv_bfloat16 g_wqih[QKV_N * DIM], g_wqil[QKV_N * DIM];
__device__ __nv_bfloat16 g_worh[DIM * DIM], g_worl[DIM * DIM];
__device__ __nv_bfloat16 g_woih[DIM * DIM], g_woil[DIM * DIM];
__device__ __nv_bfloat16 g_qph[PACKED_ELEMS], g_qpl[PACKED_ELEMS];
__device__ __nv_bfloat16 g_kph[PACKED_ELEMS], g_kpl[PACKED_ELEMS];
__device__ __nv_bfloat16 g_vrh[V_ELEMS], g_vrl[V_ELEMS];
__device__ __nv_bfloat16 g_vih[V_ELEMS], g_vil[V_ELEMS];
__device__ __nv_bfloat16 g_oarh[OUT_ELEMS], g_oarl[OUT_ELEMS];
__device__ __nv_bfloat16 g_oaih[OUT_ELEMS], g_oail[OUT_ELEMS];

// ---------------- helpers ----------------
__device__ __forceinline__ uint32_t smem_u32(const void* p) {
    uint32_t a;
    asm("{ .reg .u64 t; cvta.to.shared.u64 t, %1; cvt.u32.u64 %0, t; }" : "=r"(a) : "l"(p));
    return a;
}
__device__ __forceinline__ void cp_async16(uint32_t dst, const void* src) {
    asm volatile("cp.async.cg.shared.global [%0], [%1], 16;" :: "r"(dst), "l"(src) : "memory");
}
#define CP_COMMIT()  asm volatile("cp.async.commit_group;" ::: "memory")
#define CP_WAIT0()   asm volatile("cp.async.wait_group 0;" ::: "memory")
#define CP_WAIT1()   asm volatile("cp.async.wait_group 1;" ::: "memory")

// NOTE: NOT volatile — pure register computation; lets ptxas schedule/interleave.
__device__ __forceinline__ void mma_bf16(float c[4], const uint32_t a[4], const uint32_t b[2]) {
    asm("mma.sync.aligned.m16n8k16.row.col.f32.bf16.bf16.f32 "
        "{%0,%1,%2,%3}, {%4,%5,%6,%7}, {%8,%9}, {%0,%1,%2,%3};"
        : "+f"(c[0]), "+f"(c[1]), "+f"(c[2]), "+f"(c[3])
        : "r"(a[0]), "r"(a[1]), "r"(a[2]), "r"(a[3]), "r"(b[0]), "r"(b[1]));
}
__device__ __forceinline__ void ldsm_x4(uint32_t r[4], uint32_t a) {
    asm volatile("ldmatrix.sync.aligned.m8n8.x4.shared.b16 {%0,%1,%2,%3}, [%4];"
                 : "=r"(r[0]), "=r"(r[1]), "=r"(r[2]), "=r"(r[3]) : "r"(a));
}
__device__ __forceinline__ void ldsm_x2(uint32_t r[2], uint32_t a) {
    asm volatile("ldmatrix.sync.aligned.m8n8.x2.shared.b16 {%0,%1}, [%2];"
                 : "=r"(r[0]), "=r"(r[1]) : "r"(a));
}
__device__ __forceinline__ void ldsm_x2t(uint32_t r[2], uint32_t a) {
    asm volatile("ldmatrix.sync.aligned.m8n8.x2.trans.shared.b16 {%0,%1}, [%2];"
                 : "=r"(r[0]), "=r"(r[1]) : "r"(a));
}
__device__ __forceinline__ uint32_t pack_bf16(float a, float b) {
    uint32_t r;   // low half = a, high half = b
    asm("cvt.rn.bf16x2.f32 %0, %1, %2;" : "=r"(r) : "f"(b), "f"(a));
    return r;
}
__device__ __forceinline__ void split2(float a, float b, uint32_t& hp, uint32_t& lp) {
    hp = pack_bf16(a, b);
    const float va = __uint_as_float(hp << 16);
    const float vb = __uint_as_float(hp & 0xffff0000u);
    lp = pack_bf16(a - va, b - vb);
}
__device__ __forceinline__ float ex2f(float x) {
    float r; asm("ex2.approx.f32 %0, %1;" : "=f"(r) : "f"(x)); return r;
}

// ---------------- fused fp32 -> bf16 hi/lo splits (one launch) ----------------
#define N_X4   1048576
#define N_WQ4  786432
#define N_WO4  262144
#define SPLIT_TOTAL (2 * N_X4 + 2 * N_WQ4 + 2 * N_WO4)

__global__ void split_all(const float* __restrict__ x_r, const float* __restrict__ x_i,
                          const float* __restrict__ wq_r, const float* __restrict__ wq_i,
                          const float* __restrict__ wo_r, const float* __restrict__ wo_i)
{
    for (int i = blockIdx.x * blockDim.x + threadIdx.x; i < SPLIT_TOTAL;
         i += gridDim.x * blockDim.x) {
        const float* src; __nv_bfloat16 *hi, *lo; int off;
        if (i < 2 * N_X4) {
            if (i < N_X4) { src = x_r; hi = g_xrh; lo = g_xrl; off = i; }
            else          { src = x_i; hi = g_xih; lo = g_xil; off = i - N_X4; }
        } else if (i < 2 * N_X4 + 2 * N_WQ4) {
            const int k = i - 2 * N_X4;
            if (k < N_WQ4) { src = wq_r; hi = g_wqrh; lo = g_wqrl; off = k; }
            else           { src = wq_i; hi = g_wqih; lo = g_wqil; off = k - N_WQ4; }
        } else {
            const int k = i - 2 * N_X4 - 2 * N_WQ4;
            if (k < N_WO4) { src = wo_r; hi = g_worh; lo = g_worl; off = k; }
            else           { src = wo_i; hi = g_woih; lo = g_woil; off = k - N_WO4; }
        }
        float4 v = ((const float4*)src)[off];
        uint2 hp, lp;
        split2(v.x, v.y, hp.x, lp.x);
        split2(v.z, v.w, hp.y, lp.y);
        ((uint2*)hi)[off] = hp;
        ((uint2*)lo)[off] = lp;
    }
}

// ============================================================
// HMMA bf16x3 GEMM, 256x128 CTA tile, term-major MMA order
// (same-acc reuse distance 8) to break RAW chains.
// ============================================================
#define A_TILE_B 20480
#define B_TILE_B 10240
#define STG_B    61440
#define GEMM_SMEM (2 * STG_B)
#define NCHUNK 32

template<int QKV>
__global__ __launch_bounds__(256, 1)
void gemm_big(const float* __restrict__ bias_r, const float* __restrict__ bias_i,
              float* __restrict__ Yr, float* __restrict__ Yi)
{
    extern __shared__ char smc[];
    const uint32_t sb = smem_u32(smc);
    const int tid = threadIdx.x;
    const int wid = tid >> 5, lid = tid & 31;
    const int wm = wid >> 1, wn = wid & 1;
    const int g = lid >> 2, tig = lid & 3;
    const int n0 = blockIdx.x * 128;
    const int m0 = blockIdx.y * 256;
    const int z  = blockIdx.z;

    const __nv_bfloat16 *Ah, *Al, *Bhp, *Blp;
    const float* bias;
    if (QKV) {
        if (z == 0) { Ah = g_xrh; Al = g_xrl; Bhp = g_wqrh; Blp = g_wqrl; bias = bias_r; }
        else        { Ah = g_xih; Al = g_xil; Bhp = g_wqih; Blp = g_wqil; bias = bias_i; }
    } else {
        if (z == 0) { Ah = g_oarh; Al = g_oarl; Bhp = g_worh; Blp = g_worl; bias = bias_r; }
        else        { Ah = g_oaih; Al = g_oail; Bhp = g_woih; Blp = g_woil; bias = bias_i; }
    }
    float* Y = (z == 0) ? Yr : Yi;

    auto issue_cp = [&](int chunk, int s) {
        const int k0 = chunk * 32;
        const uint32_t base = sb + (uint32_t)s * STG_B;
#pragma unroll
        for (int i = 0; i < 12; ++i) {
            const int lin = tid + i * 256;
            if (lin < 2048) {
                const int hl = lin >> 10, rc = lin & 1023;
                const int row = rc >> 2, c = rc & 3;
                cp_async16(base + hl * A_TILE_B + row * 80 + c * 16,
                           (hl ? Al : Ah) + (size_t)(m0 + row) * DIM + k0 + c * 8);
            } else {
                const int l2 = lin - 2048;
                const int hl = l2 >> 9, rc = l2 & 511;
                const int row = rc >> 2, c = rc & 3;
                cp_async16(base + 2 * A_TILE_B + hl * B_TILE_B + row * 80 + c * 16,
                           (hl ? Blp : Bhp) + (size_t)(n0 + row) * DIM + k0 + c * 8);
            }
        }
    };

    const uint32_t a_rel = (uint32_t)((wm * 64 + (lid & 15)) * 80 + ((lid >> 4) << 4));
    const uint32_t b_rel = (uint32_t)((wn * 64 + (lid & 7) + ((lid & 16) >> 1)) * 80 +
                                      ((lid & 8) << 1));

    float acc[4][8][4];
#pragma unroll
    for (int a = 0; a < 4; a++)
#pragma unroll
        for (int b = 0; b < 8; b++)
#pragma unroll
            for (int c = 0; c < 4; c++) acc[a][b][c] = 0.f;

    issue_cp(0, 0);
    CP_COMMIT();

    for (int j = 0; j < NCHUNK; ++j) {
        if (j + 1 < NCHUNK) {
            issue_cp(j + 1, (j + 1) & 1);
            CP_COMMIT();
            CP_WAIT1();
        } else {
            CP_WAIT0();
        }
        __syncthreads();

        const uint32_t st  = sb + (uint32_t)(j & 1) * STG_B;
        const uint32_t aAh = st + a_rel;
        const uint32_t aAl = aAh + A_TILE_B;
        const uint32_t aBh = st + 2 * A_TILE_B + b_rel;
        const uint32_t aBl = aBh + B_TILE_B;

#pragma unroll
        for (int ks = 0; ks < 2; ++ks) {
            uint32_t bh_[4][4], bl_[4][4];
#pragma unroll
            for (int nb2 = 0; nb2 < 4; ++nb2) {
                ldsm_x4(bh_[nb2], aBh + nb2 * 1280 + ks * 32);
                ldsm_x4(bl_[nb2], aBl + nb2 * 1280 + ks * 32);
            }
#pragma unroll
            for (int mi = 0; mi < 4; ++mi) {
                uint32_t ah[4], al[4];
                ldsm_x4(ah, aAh + mi * 1280 + ks * 32);
                ldsm_x4(al, aAl + mi * 1280 + ks * 32);
                // term-major: same accumulator re-used at distance 8
#pragma unroll
                for (int nb2 = 0; nb2 < 4; ++nb2) {
                    mma_bf16(acc[mi][2 * nb2],     ah, bh_[nb2]);
                    mma_bf16(acc[mi][2 * nb2 + 1], ah, bh_[nb2] + 2);
                }
#pragma unroll
                for (int nb2 = 0; nb2 < 4; ++nb2) {
                    mma_bf16(acc[mi][2 * nb2],     ah, bl_[nb2]);
                    mma_bf16(acc[mi][2 * nb2 + 1], ah, bl_[nb2] + 2);
                }
#pragma unroll
                for (int nb2 = 0; nb2 < 4; ++nb2) {
                    mma_bf16(acc[mi][2 * nb2],     al, bh_[nb2]);
                    mma_bf16(acc[mi][2 * nb2 + 1], al, bh_[nb2] + 2);
                }
            }
        }
        __syncthreads();
    }

    // ---- epilogue ----
#pragma unroll
    for (int nb = 0; nb < 8; ++nb) {
        const int n = n0 + wn * 64 + nb * 8 + tig * 2;
        const float b0v = bias[n], b1v = bias[n + 1];
#pragma unroll
        for (int mi = 0; mi < 4; ++mi) {
            const int mlo = m0 + wm * 64 + mi * 16 + g;
#pragma unroll
            for (int half = 0; half < 2; ++half) {
                const int m = mlo + half * 8;
                const float y0 = acc[mi][nb][half * 2 + 0] + b0v;
                const float y1 = acc[mi][nb][half * 2 + 1] + b1v;
                if (!QKV) {
                    *(float2*)&Y[(size_t)m * DIM + n] = make_float2(y0, y1);
                } else {
                    uint32_t hp, lp;
                    split2(y0, y1, hp, lp);
                    const int which = n >> 10;
                    const int h = (n >> 6) & 15;
                    const int d = n & 63;
                    const int bh = (m >> 11) * HEADS + h;
                    const int ns = m & 2047;
                    if (which == 2) {
                        const size_t idx = ((size_t)bh * SEQ + ns) * HD + d;
                        if (z == 0) {
                            *(uint32_t*)&g_vrh[idx] = hp;
                            *(uint32_t*)&g_vrl[idx] = lp;
                        } else {
                            *(uint32_t*)&g_vih[idx] = hp;
                            *(uint32_t*)&g_vil[idx] = lp;
                        }
                    } else {
                        const size_t idx = ((size_t)bh * SEQ + ns) * 128 + d + (z ? 64 : 0);
                        if (which == 0) {
                            *(uint32_t*)&g_qph[idx] = hp;
                            *(uint32_t*)&g_qpl[idx] = lp;
                        } else {
                            *(uint32_t*)&g_kph[idx] = hp;
                            *(uint32_t*)&g_kpl[idx] = lp;
                        }
                    }
                }
            }
        }
    }
}

// ============================================================
// HMMA flash complex attention (bf16x3), no-max softmax,
// Sr/Si and Or/Oi MMA chains interleaved (distance >= 2).
// ============================================================
#define NT 32
#define QSM_H 0u
#define QSM_L 17408u
#define KSM_H 34816u
#define KSM_L 52224u
#define VSM(b) (69632u + (uint32_t)(b) * 9216u)
#define ATT_SMEM 106496

__global__ __launch_bounds__(128, 2)
void attn_mma()
{
    extern __shared__ char smb[];
    const uint32_t sb = smem_u32(smb);
    const int tid = threadIdx.x, w = tid >> 5, L = tid & 31;
    const int bh = blockIdx.y, qt = blockIdx.x;
    const size_t kvrow0 = (size_t)bh * SEQ;

    auto issueQ = [&]() {
        const size_t qb = (kvrow0 + (size_t)qt * 64) * 128;
#pragma unroll
        for (int i = 0; i < 16; ++i) {
            const int lin = tid + i * 128;
            const int hl = lin >> 10, rem = lin & 1023, row = rem >> 4, ch = rem & 15;
            const __nv_bfloat16* src = (hl ? g_qpl : g_qph) + qb + row * 128 + ch * 8;
            cp_async16(sb + (hl ? QSM_L : QSM_H) + row * 272 + ch * 16, src);
        }
    };
    auto issueK = [&](int kt) {
#pragma unroll
        for (int i = 0; i < 16; ++i) {
            const int lin = tid + i * 128;
            const int hl = lin >> 10, rem = lin & 1023, row = rem >> 4, ch = rem & 15;
            const __nv_bfloat16* src = (hl ? g_kpl : g_kph) + (kvrow0 + kt * 64 + row) * 128 + ch * 8;
            cp_async16(sb + (hl ? KSM_L : KSM_H) + row * 272 + ch * 16, src);
        }
    };
    auto issueV = [&](int kt) {
        const __nv_bfloat16* bufs[4] = { g_vrh, g_vrl, g_vih, g_vil };
#pragma unroll
        for (int i = 0; i < 16; ++i) {
            const int lin = tid + i * 128;
            const int bf = lin >> 9, rem = lin & 511, row = rem >> 3, ch = rem & 7;
            cp_async16(sb + VSM(bf) + row * 144 + ch * 16,
                       bufs[bf] + (kvrow0 + kt * 64 + row) * HD + ch * 8);
        }
    };

    float Or[8][4], Oi[8][4];
#pragma unroll
    for (int nb = 0; nb < 8; ++nb)
#pragma unroll
        for (int e = 0; e < 4; ++e) { Or[nb][e] = 0.f; Oi[nb][e] = 0.f; }
    float l0 = 0.f, l1 = 0.f;

    const uint32_t a_off = (uint32_t)((w * 16 + (L & 7) + (L & 8)) * 272 + ((L & 16) ? 16 : 0));
    const uint32_t brow  = (uint32_t)((L & 7) * 272 + ((L & 8) ? 16 : 0));
    const uint32_t vrow  = (uint32_t)(((L & 7) + (L & 8)) * 144);

    issueQ(); issueK(0); CP_COMMIT();
    issueV(0); CP_COMMIT();

    for (int j = 0; j < NT; ++j) {
        CP_WAIT1();
        __syncthreads();

        float Sr[8][4], Si[8][4];
#pragma unroll
        for (int nb = 0; nb < 8; ++nb)
#pragma unroll
            for (int e = 0; e < 4; ++e) { Sr[nb][e] = 0.f; Si[nb][e] = 0.f; }

#pragma unroll
        for (int c = 0; c < 4; ++c) {
            uint32_t fh[4], fl[4], gh[4], gl[4], nh[4], nl[4];
            ldsm_x4(fh, sb + QSM_H + a_off + c * 32);
            ldsm_x4(fl, sb + QSM_L + a_off + c * 32);
            ldsm_x4(gh, sb + QSM_H + a_off + (c + 4) * 32);
            ldsm_x4(gl, sb + QSM_L + a_off + (c + 4) * 32);
#pragma unroll
            for (int r = 0; r < 4; ++r) { nh[r] = fh[r] ^ 0x80008000u; nl[r] = fl[r] ^ 0x80008000u; }
#pragma unroll
            for (int nb = 0; nb < 8; ++nb) {
                const uint32_t ba = (uint32_t)nb * 2176u + brow;
                uint32_t bch[2], bcl[2], bdh[2], bdl[2];
                ldsm_x2(bch, sb + KSM_H + ba + c * 32);
                ldsm_x2(bcl, sb + KSM_L + ba + c * 32);
                ldsm_x2(bdh, sb + KSM_H + ba + (c + 4) * 32);
                ldsm_x2(bdl, sb + KSM_L + ba + (c + 4) * 32);
                // interleaved Sr/Si: same-acc distance 2
                mma_bf16(Sr[nb], fh, bch); mma_bf16(Si[nb], gh, bch);
                mma_bf16(Sr[nb], fh, bcl); mma_bf16(Si[nb], gh, bcl);
                mma_bf16(Sr[nb], fl, bch); mma_bf16(Si[nb], gl, bch);
                mma_bf16(Sr[nb], gh, bdh); mma_bf16(Si[nb], nh, bdh);
                mma_bf16(Sr[nb], gh, bdl); mma_bf16(Si[nb], nh, bdl);
                mma_bf16(Sr[nb], gl, bdh); mma_bf16(Si[nb], nl, bdh);
            }
        }
        __syncthreads();

        if (j + 1 < NT) { issueK(j + 1); CP_COMMIT(); }

#pragma unroll
        for (int nb = 0; nb < 8; ++nb)
#pragma unroll
            for (int e = 0; e < 4; ++e) {
                const float x = fmaf(Sr[nb][e], Sr[nb][e], Si[nb][e] * Si[nb][e]);
                float rs; asm("rsqrt.approx.f32 %0, %1;" : "=f"(rs) : "f"(x + 1e-30f));
                const float p = ex2f((EXP_C * x) * rs);
                Sr[nb][e] = p;
                if (e < 2) l0 += p; else l1 += p;
            }

        uint32_t Ph[4][4], Pl[4][4];
#pragma unroll
        for (int kc = 0; kc < 4; ++kc) {
            split2(Sr[2 * kc][0],     Sr[2 * kc][1],     Ph[kc][0], Pl[kc][0]);
            split2(Sr[2 * kc][2],     Sr[2 * kc][3],     Ph[kc][1], Pl[kc][1]);
            split2(Sr[2 * kc + 1][0], Sr[2 * kc + 1][1], Ph[kc][2], Pl[kc][2]);
            split2(Sr[2 * kc + 1][2], Sr[2 * kc + 1][3], Ph[kc][3], Pl[kc][3]);
        }

        if (j + 1 < NT) { CP_WAIT1(); } else { CP_WAIT0(); }
        __syncthreads();

#pragma unroll
        for (int kc = 0; kc < 4; ++kc) {
            const uint32_t va = vrow + (uint32_t)kc * 2304u;
#pragma unroll
            for (int nb = 0; nb < 8; ++nb) {
                uint32_t vrh_[2], vrl_[2], vih_[2], vil_[2];
                ldsm_x2t(vrh_, sb + VSM(0) + va + nb * 16);
                ldsm_x2t(vrl_, sb + VSM(1) + va + nb * 16);
                ldsm_x2t(vih_, sb + VSM(2) + va + nb * 16);
                ldsm_x2t(vil_, sb + VSM(3) + va + nb * 16);
                // interleaved Or/Oi: same-acc distance 2
                mma_bf16(Or[nb], Ph[kc], vrh_); mma_bf16(Oi[nb], Ph[kc], vih_);
                mma_bf16(Or[nb], Ph[kc], vrl_); mma_bf16(Oi[nb], Ph[kc], vil_);
                mma_bf16(Or[nb], Pl[kc], vrh_); mma_bf16(Oi[nb], Pl[kc], vih_);
            }
        }
        __syncthreads();

        if (j + 1 < NT) { issueV(j + 1); CP_COMMIT(); }
    }

    l0 += __shfl_xor_sync(0xffffffffu, l0, 1);
    l0 += __shfl_xor_sync(0xffffffffu, l0, 2);
    l1 += __shfl_xor_sync(0xffffffffu, l1, 1);
    l1 += __shfl_xor_sync(0xffffffffu, l1, 2);
    const float inv0 = 1.f / l0, inv1 = 1.f / l1;
    const int b  = bh >> 4;
    const int hh = bh & 15;
    const int r0 = qt * 64 + w * 16 + (L >> 2);
    const size_t base0 = ((size_t)b * SEQ + r0) * DIM + hh * 64;
    const size_t base1 = base0 + (size_t)8 * DIM;
#pragma unroll
    for (int nb = 0; nb < 8; ++nb) {
        const int col = nb * 8 + 2 * (L & 3);
        uint32_t hp, lp;
        split2(Or[nb][0] * inv0, Or[nb][1] * inv0, hp, lp);
        *(uint32_t*)&g_oarh[base0 + col] = hp;  *(uint32_t*)&g_oarl[base0 + col] = lp;
        split2(Oi[nb][0] * inv0, Oi[nb][1] * inv0, hp, lp);
        *(uint32_t*)&g_oaih[base0 + col] = hp;  *(uint32_t*)&g_oail[base0 + col] = lp;
        split2(Or[nb][2] * inv1, Or[nb][3] * inv1, hp, lp);
        *(uint32_t*)&g_oarh[base1 + col] = hp;  *(uint32_t*)&g_oarl[base1 + col] = lp;
        split2(Oi[nb][2] * inv1, Oi[nb][3] * inv1, hp, lp);
        *(uint32_t*)&g_oaih[base1 + col] = hp;  *(uint32_t*)&g_oail[base1 + col] = lp;
    }
}

// ============================================================
extern "C" void kernel_launch(void* const* d_in, const int* in_sizes, int n_in,
                              void* d_out, int out_size)
{
    const float* x_r    = (const float*)d_in[0];
    const float* x_i    = (const float*)d_in[1];
    const float* Wqkv_r = (const float*)d_in[2];
    const float* bqkv_r = (const float*)d_in[3];
    const float* Wqkv_i = (const float*)d_in[4];
    const float* bqkv_i = (const float*)d_in[5];
    const float* Wout_r = (const float*)d_in[6];
    const float* bout_r = (const float*)d_in[7];
    const float* Wout_i = (const float*)d_in[8];
    const float* bout_i = (const float*)d_in[9];

    cudaFuncSetAttribute(gemm_big<1>, cudaFuncAttributeMaxDynamicSharedMemorySize, GEMM_SMEM);
    cudaFuncSetAttribute(gemm_big<0>, cudaFuncAttributeMaxDynamicSharedMemorySize, GEMM_SMEM);
    cudaFuncSetAttribute(attn_mma,    cudaFuncAttributeMaxDynamicSharedMemorySize, ATT_SMEM);

    // 1) fused splits
    split_all<<<2048, 256>>>(x_r, x_i, Wqkv_r, Wqkv_i, Wout_r, Wout_i);

    // 2) QKV projections (real + imag in one launch)
    dim3 gq(QKV_N / 128, M_TOTAL / 256, 2);
    gemm_big<1><<<gq, 256, GEMM_SMEM>>>(bqkv_r, bqkv_i, nullptr, nullptr);

    // 3) HMMA flash complex attention
    dim3 ga(SEQ / 64, BH);
    attn_mma<<<ga, 128, ATT_SMEM>>>();

    // 4) output projections (real + imag in one launch)
    float* outr = (float*)d_out;
    float* outi = outr + (size_t)OUT_ELEMS;
    dim3 go(DIM / 128, M_TOTAL / 256, 2);
    gemm_big<0><<<go, 256, GEMM_SMEM>>>(bout_r, bout_i, outr, outi);
}

// round 10
// speedup vs baseline: 1.5361x; 1.5084x over previous
#include <cuda_runtime.h>
#include <cuda_fp16.h>
#include <cstdint>
#include <math.h>

#define B_SZ   2
#define SEQ    2048
#define DIM    1024
#define HEADS  16
#define HD     64
#define SCALE  0.125f
#define EXP_C  0.1803368801111243f   /* SCALE * log2(e) */
#define PBIAS  4.0f                  /* p' = 2^(C*mag - PBIAS), cancels in O/l */
#define M_TOTAL (B_SZ * SEQ)
#define QKV_N   (3 * DIM)
#define OUT_ELEMS  (B_SZ * SEQ * DIM)
#define BH      (B_SZ * HEADS)
#define PACKED_ELEMS (BH * SEQ * 128)
#define V_ELEMS      (BH * SEQ * HD)

// ---------------- scratch (static device globals, fp16) ----------------
__device__ __half g_xrh[OUT_ELEMS], g_xih[OUT_ELEMS];                  // x plain
__device__ __half g_wqrh[QKV_N * DIM], g_wqrl[QKV_N * DIM];            // Wqkv hi/lo
__device__ __half g_wqih[QKV_N * DIM], g_wqil[QKV_N * DIM];
__device__ __half g_worh[DIM * DIM], g_worl[DIM * DIM];                // Wout hi/lo
__device__ __half g_woih[DIM * DIM], g_woil[DIM * DIM];
__device__ __half g_qph[PACKED_ELEMS], g_qpl[PACKED_ELEMS];            // Q hi/lo packed
__device__ __half g_kph[PACKED_ELEMS];                                 // K plain packed
__device__ __half g_vrh[V_ELEMS], g_vrl[V_ELEMS];                      // V hi/lo
__device__ __half g_vih[V_ELEMS], g_vil[V_ELEMS];
__device__ __half g_oarh[OUT_ELEMS], g_oaih[OUT_ELEMS];                // O plain

// ---------------- helpers ----------------
__device__ __forceinline__ uint32_t smem_u32(const void* p) {
    uint32_t a;
    asm("{ .reg .u64 t; cvta.to.shared.u64 t, %1; cvt.u32.u64 %0, t; }" : "=r"(a) : "l"(p));
    return a;
}
__device__ __forceinline__ void cp_async16(uint32_t dst, const void* src) {
    asm volatile("cp.async.cg.shared.global [%0], [%1], 16;" :: "r"(dst), "l"(src) : "memory");
}
#define CP_COMMIT()  asm volatile("cp.async.commit_group;" ::: "memory")
#define CP_WAIT0()   asm volatile("cp.async.wait_group 0;" ::: "memory")
#define CP_WAIT1()   asm volatile("cp.async.wait_group 1;" ::: "memory")

__device__ __forceinline__ void mma_f16(float c[4], const uint32_t a[4], const uint32_t b[2]) {
    asm("mma.sync.aligned.m16n8k16.row.col.f32.f16.f16.f32 "
        "{%0,%1,%2,%3}, {%4,%5,%6,%7}, {%8,%9}, {%0,%1,%2,%3};"
        : "+f"(c[0]), "+f"(c[1]), "+f"(c[2]), "+f"(c[3])
        : "r"(a[0]), "r"(a[1]), "r"(a[2]), "r"(a[3]), "r"(b[0]), "r"(b[1]));
}
__device__ __forceinline__ void ldsm_x4(uint32_t r[4], uint32_t a) {
    asm volatile("ldmatrix.sync.aligned.m8n8.x4.shared.b16 {%0,%1,%2,%3}, [%4];"
                 : "=r"(r[0]), "=r"(r[1]), "=r"(r[2]), "=r"(r[3]) : "r"(a));
}
__device__ __forceinline__ void ldsm_x2(uint32_t r[2], uint32_t a) {
    asm volatile("ldmatrix.sync.aligned.m8n8.x2.shared.b16 {%0,%1}, [%2];"
                 : "=r"(r[0]), "=r"(r[1]) : "r"(a));
}
__device__ __forceinline__ void ldsm_x2t(uint32_t r[2], uint32_t a) {
    asm volatile("ldmatrix.sync.aligned.m8n8.x2.trans.shared.b16 {%0,%1}, [%2];"
                 : "=r"(r[0]), "=r"(r[1]) : "r"(a));
}
__device__ __forceinline__ uint32_t packh(float a, float b) {
    __half2 h = __floats2half2_rn(a, b);
    return *reinterpret_cast<uint32_t*>(&h);
}
__device__ __forceinline__ void split2h(float a, float b, uint32_t& hp, uint32_t& lp) {
    __half2 h = __floats2half2_rn(a, b);
    hp = *reinterpret_cast<uint32_t*>(&h);
    const float ra = a - __half2float(__low2half(h));
    const float rb = b - __half2float(__high2half(h));
    __half2 l = __floats2half2_rn(ra, rb);
    lp = *reinterpret_cast<uint32_t*>(&l);
}
__device__ __forceinline__ float ex2f(float x) {
    float r; asm("ex2.approx.f32 %0, %1;" : "=f"(r) : "f"(x)); return r;
}

// ---------------- fused fp32 -> fp16 conversions (one launch) ----------------
#define N_X4   1048576      /* OUT_ELEMS/4     */
#define N_WQ4  786432       /* QKV_N*DIM/4     */
#define N_WO4  262144       /* DIM*DIM/4       */
#define SPLIT_TOTAL (2 * N_X4 + 2 * N_WQ4 + 2 * N_WO4)

__global__ void split_all(const float* __restrict__ x_r, const float* __restrict__ x_i,
                          const float* __restrict__ wq_r, const float* __restrict__ wq_i,
                          const float* __restrict__ wo_r, const float* __restrict__ wo_i)
{
    for (int i = blockIdx.x * blockDim.x + threadIdx.x; i < SPLIT_TOTAL;
         i += gridDim.x * blockDim.x) {
        if (i < 2 * N_X4) {                 // x: plain fp16
            const float* src = (i < N_X4) ? x_r : x_i;
            __half* hi = (i < N_X4) ? g_xrh : g_xih;
            const int off = (i < N_X4) ? i : i - N_X4;
            float4 v = ((const float4*)src)[off];
            uint2 hp;
            hp.x = packh(v.x, v.y); hp.y = packh(v.z, v.w);
            ((uint2*)hi)[off] = hp;
        } else {                            // weights: hi/lo
            const float* src; __half *hi, *lo; int off;
            if (i < 2 * N_X4 + 2 * N_WQ4) {
                const int k = i - 2 * N_X4;
                if (k < N_WQ4) { src = wq_r; hi = g_wqrh; lo = g_wqrl; off = k; }
                else           { src = wq_i; hi = g_wqih; lo = g_wqil; off = k - N_WQ4; }
            } else {
                const int k = i - 2 * N_X4 - 2 * N_WQ4;
                if (k < N_WO4) { src = wo_r; hi = g_worh; lo = g_worl; off = k; }
                else           { src = wo_i; hi = g_woih; lo = g_woil; off = k - N_WO4; }
            }
            float4 v = ((const float4*)src)[off];
            uint2 hp, lp;
            split2h(v.x, v.y, hp.x, lp.x);
            split2h(v.z, v.w, hp.y, lp.y);
            ((uint2*)hi)[off] = hp;
            ((uint2*)lo)[off] = lp;
        }
    }
}

// ============================================================
// HMMA fp16 2-term GEMM: D = A @ (Bh+Bl)^T + bias.
// A plain fp16, B fp16 hi/lo. CTA 128x128, K-chunk 32,
// 2-stage cp.async, 8 warps (2x4), warp tile 64x32, 2 CTA/SM.
// ============================================================
#define T128_B 10240                   /* 128 rows x 80 B */
#define STG_B  (3 * T128_B)            /* A, Bh, Bl       */
#define GEMM_SMEM (2 * STG_B)          /* 61440           */
#define NCHUNK 32

template<int QKV>
__global__ __launch_bounds__(256, 2)
void gemm_f16(const float* __restrict__ bias_r, const float* __restrict__ bias_i,
              float* __restrict__ Yr, float* __restrict__ Yi)
{
    extern __shared__ char smc[];
    const uint32_t sb = smem_u32(smc);
    const int tid = threadIdx.x;
    const int wid = tid >> 5, lid = tid & 31;
    const int wm = wid >> 2, wn = wid & 3;       // 2 x 4 warp grid
    const int g = lid >> 2, tig = lid & 3;
    const int n0 = blockIdx.x * 128;
    const int m0 = blockIdx.y * 128;
    const int z  = blockIdx.z;

    const __half *A, *Bh, *Bl;
    const float* bias;
    if (QKV) {
        if (z == 0) { A = g_xrh;  Bh = g_wqrh; Bl = g_wqrl; bias = bias_r; }
        else        { A = g_xih;  Bh = g_wqih; Bl = g_wqil; bias = bias_i; }
    } else {
        if (z == 0) { A = g_oarh; Bh = g_worh; Bl = g_worl; bias = bias_r; }
        else        { A = g_oaih; Bh = g_woih; Bl = g_woil; bias = bias_i; }
    }
    float* Y = (z == 0) ? Yr : Yi;

    auto issue_cp = [&](int chunk, int s) {
        const int k0 = chunk * 32;
        const uint32_t base = sb + (uint32_t)s * STG_B;
#pragma unroll
        for (int i = 0; i < 6; ++i) {
            const int lin = tid + i * 256;           // 0..1535
            if (lin < 512) {                          // A
                const int row = lin >> 2, c = lin & 3;
                cp_async16(base + row * 80 + c * 16,
                           A + (size_t)(m0 + row) * DIM + k0 + c * 8);
            } else {                                  // Bh / Bl
                const int l2 = lin - 512;
                const int hl = l2 >> 9, rc = l2 & 511;
                const int row = rc >> 2, c = rc & 3;
                cp_async16(base + T128_B + hl * T128_B + row * 80 + c * 16,
                           (hl ? Bl : Bh) + (size_t)(n0 + row) * DIM + k0 + c * 8);
            }
        }
    };

    const uint32_t a_rel = (uint32_t)((wm * 64 + (lid & 15)) * 80 + ((lid >> 4) << 4));
    const uint32_t b_rel = (uint32_t)((wn * 32 + (lid & 7) + ((lid & 16) >> 1)) * 80 +
                                      ((lid & 8) << 1));

    float acc[4][4][4];
#pragma unroll
    for (int a = 0; a < 4; a++)
#pragma unroll
        for (int b = 0; b < 4; b++)
#pragma unroll
            for (int c = 0; c < 4; c++) acc[a][b][c] = 0.f;

    issue_cp(0, 0);
    CP_COMMIT();

    for (int j = 0; j < NCHUNK; ++j) {
        if (j + 1 < NCHUNK) {
            issue_cp(j + 1, (j + 1) & 1);
            CP_COMMIT();
            CP_WAIT1();
        } else {
            CP_WAIT0();
        }
        __syncthreads();

        const uint32_t st  = sb + (uint32_t)(j & 1) * STG_B;
        const uint32_t aA  = st + a_rel;
        const uint32_t aBh = st + T128_B + b_rel;
        const uint32_t aBl = aBh + T128_B;

#pragma unroll
        for (int ks = 0; ks < 2; ++ks) {
            uint32_t bh01[4], bh23[4], bl01[4], bl23[4];
            ldsm_x4(bh01, aBh + ks * 32);
            ldsm_x4(bh23, aBh + 1280 + ks * 32);
            ldsm_x4(bl01, aBl + ks * 32);
            ldsm_x4(bl23, aBl + 1280 + ks * 32);
#pragma unroll
            for (int mi = 0; mi < 4; ++mi) {
                uint32_t ah[4];
                ldsm_x4(ah, aA + mi * 1280 + ks * 32);
                mma_f16(acc[mi][0], ah, bh01);
                mma_f16(acc[mi][1], ah, bh01 + 2);
                mma_f16(acc[mi][2], ah, bh23);
                mma_f16(acc[mi][3], ah, bh23 + 2);
                mma_f16(acc[mi][0], ah, bl01);
                mma_f16(acc[mi][1], ah, bl01 + 2);
                mma_f16(acc[mi][2], ah, bl23);
                mma_f16(acc[mi][3], ah, bl23 + 2);
            }
        }
        __syncthreads();
    }

    // ---- epilogue ----
#pragma unroll
    for (int nb = 0; nb < 4; ++nb) {
        const int n = n0 + wn * 32 + nb * 8 + tig * 2;
        const float b0v = bias[n], b1v = bias[n + 1];
#pragma unroll
        for (int mi = 0; mi < 4; ++mi) {
            const int mlo = m0 + wm * 64 + mi * 16 + g;
#pragma unroll
            for (int half = 0; half < 2; ++half) {
                const int m = mlo + half * 8;
                const float y0 = acc[mi][nb][half * 2 + 0] + b0v;
                const float y1 = acc[mi][nb][half * 2 + 1] + b1v;
                if (!QKV) {
                    *(float2*)&Y[(size_t)m * DIM + n] = make_float2(y0, y1);
                } else {
                    const int which = n >> 10;
                    const int h = (n >> 6) & 15;
                    const int d = n & 63;
                    const int bh = (m >> 11) * HEADS + h;
                    const int ns = m & 2047;
                    if (which == 2) {                  // V: hi/lo
                        uint32_t hp, lp;
                        split2h(y0, y1, hp, lp);
                        const size_t idx = ((size_t)bh * SEQ + ns) * HD + d;
                        if (z == 0) {
                            *(uint32_t*)&g_vrh[idx] = hp;
                            *(uint32_t*)&g_vrl[idx] = lp;
                        } else {
                            *(uint32_t*)&g_vih[idx] = hp;
                            *(uint32_t*)&g_vil[idx] = lp;
                        }
                    } else {
                        const size_t idx = ((size_t)bh * SEQ + ns) * 128 + d + (z ? 64 : 0);
                        if (which == 0) {              // Q: hi/lo
                            uint32_t hp, lp;
                            split2h(y0, y1, hp, lp);
                            *(uint32_t*)&g_qph[idx] = hp;
                            *(uint32_t*)&g_qpl[idx] = lp;
                        } else {                       // K: plain
                            *(uint32_t*)&g_kph[idx] = packh(y0, y1);
                        }
                    }
                }
            }
        }
    }
}

// ============================================================
// HMMA flash complex attention: Q fp16x2, K plain, P plain
// (biased by 2^-PBIAS), V fp16x2. No-max softmax.
// Grid (32 qtiles, 32 bh), 128 threads, 2 CTAs/SM.
// ============================================================
#define NT 32
#define QSM_H 0u
#define QSM_L 17408u
#define KSM   34816u
#define VSM(b) (52224u + (uint32_t)(b) * 9216u)
#define ATT_SMEM 89088

__global__ __launch_bounds__(128, 2)
void attn_mma()
{
    extern __shared__ char smb[];
    const uint32_t sb = smem_u32(smb);
    const int tid = threadIdx.x, w = tid >> 5, L = tid & 31;
    const int bh = blockIdx.y, qt = blockIdx.x;
    const size_t kvrow0 = (size_t)bh * SEQ;

    auto issueQ = [&]() {
        const size_t qb = (kvrow0 + (size_t)qt * 64) * 128;
#pragma unroll
        for (int i = 0; i < 16; ++i) {
            const int lin = tid + i * 128;
            const int hl = lin >> 10, rem = lin & 1023, row = rem >> 4, ch = rem & 15;
            const __half* src = (hl ? g_qpl : g_qph) + qb + row * 128 + ch * 8;
            cp_async16(sb + (hl ? QSM_L : QSM_H) + row * 272 + ch * 16, src);
        }
    };
    auto issueK = [&](int kt) {
#pragma unroll
        for (int i = 0; i < 8; ++i) {
            const int lin = tid + i * 128;
            const int row = lin >> 4, ch = lin & 15;
            cp_async16(sb + KSM + row * 272 + ch * 16,
                       g_kph + (kvrow0 + kt * 64 + row) * 128 + ch * 8);
        }
    };
    auto issueV = [&](int kt) {
        const __half* bufs[4] = { g_vrh, g_vrl, g_vih, g_vil };
#pragma unroll
        for (int i = 0; i < 16; ++i) {
            const int lin = tid + i * 128;
            const int bf = lin >> 9, rem = lin & 511, row = rem >> 3, ch = rem & 7;
            cp_async16(sb + VSM(bf) + row * 144 + ch * 16,
                       bufs[bf] + (kvrow0 + kt * 64 + row) * HD + ch * 8);
        }
    };

    float Or[8][4], Oi[8][4];
#pragma unroll
    for (int nb = 0; nb < 8; ++nb)
#pragma unroll
        for (int e = 0; e < 4; ++e) { Or[nb][e] = 0.f; Oi[nb][e] = 0.f; }
    float l0 = 0.f, l1 = 0.f;

    const uint32_t a_off = (uint32_t)((w * 16 + (L & 7) + (L & 8)) * 272 + ((L & 16) ? 16 : 0));
    const uint32_t brow  = (uint32_t)((L & 7) * 272 + ((L & 8) ? 16 : 0));
    const uint32_t vrow  = (uint32_t)(((L & 7) + (L & 8)) * 144);

    issueQ(); issueK(0); CP_COMMIT();
    issueV(0); CP_COMMIT();

    for (int j = 0; j < NT; ++j) {
        CP_WAIT1();
        __syncthreads();

        float Sr[8][4], Si[8][4];
#pragma unroll
        for (int nb = 0; nb < 8; ++nb)
#pragma unroll
            for (int e = 0; e < 4; ++e) { Sr[nb][e] = 0.f; Si[nb][e] = 0.f; }

        // ---- scores: Sr = [Qr|Qi]·K^T (x2 on Q), Si = [Qi|-Qr]·K^T ----
#pragma unroll
        for (int c = 0; c < 4; ++c) {
            uint32_t fh[4], fl[4], gh[4], gl[4], nh[4], nl[4];
            ldsm_x4(fh, sb + QSM_H + a_off + c * 32);
            ldsm_x4(fl, sb + QSM_L + a_off + c * 32);
            ldsm_x4(gh, sb + QSM_H + a_off + (c + 4) * 32);
            ldsm_x4(gl, sb + QSM_L + a_off + (c + 4) * 32);
#pragma unroll
            for (int r = 0; r < 4; ++r) { nh[r] = fh[r] ^ 0x80008000u; nl[r] = fl[r] ^ 0x80008000u; }
#pragma unroll
            for (int nb = 0; nb < 8; ++nb) {
                const uint32_t ba = (uint32_t)nb * 2176u + brow;
                uint32_t bc[2], bd[2];
                ldsm_x2(bc, sb + KSM + ba + c * 32);
                ldsm_x2(bd, sb + KSM + ba + (c + 4) * 32);
                mma_f16(Sr[nb], fh, bc); mma_f16(Si[nb], gh, bc);
                mma_f16(Sr[nb], fl, bc); mma_f16(Si[nb], gl, bc);
                mma_f16(Sr[nb], gh, bd); mma_f16(Si[nb], nh, bd);
                mma_f16(Sr[nb], gl, bd); mma_f16(Si[nb], nl, bd);
            }
        }
        __syncthreads();

        if (j + 1 < NT) { issueK(j + 1); CP_COMMIT(); }

        // ---- no-max softmax: p' = 2^(C*mag - PBIAS) ----
#pragma unroll
        for (int nb = 0; nb < 8; ++nb)
#pragma unroll
            for (int e = 0; e < 4; ++e) {
                const float x = fmaf(Sr[nb][e], Sr[nb][e], Si[nb][e] * Si[nb][e]);
                float rs; asm("rsqrt.approx.f32 %0, %1;" : "=f"(rs) : "f"(x + 1e-30f));
                const float p = ex2f((EXP_C * x) * rs - PBIAS);
                Sr[nb][e] = p;
                if (e < 2) l0 += p; else l1 += p;
            }

        // ---- pack P (plain fp16) ----
        uint32_t Pf[4][4];
#pragma unroll
        for (int kc = 0; kc < 4; ++kc) {
            Pf[kc][0] = packh(Sr[2 * kc][0],     Sr[2 * kc][1]);
            Pf[kc][1] = packh(Sr[2 * kc][2],     Sr[2 * kc][3]);
            Pf[kc][2] = packh(Sr[2 * kc + 1][0], Sr[2 * kc + 1][1]);
            Pf[kc][3] = packh(Sr[2 * kc + 1][2], Sr[2 * kc + 1][3]);
        }

        if (j + 1 < NT) { CP_WAIT1(); } else { CP_WAIT0(); }
        __syncthreads();

        // ---- PV: O += P @ (Vh + Vl) ----
#pragma unroll
        for (int kc = 0; kc < 4; ++kc) {
            const uint32_t va = vrow + (uint32_t)kc * 2304u;
#pragma unroll
            for (int nb = 0; nb < 8; ++nb) {
                uint32_t vrh_[2], vrl_[2], vih_[2], vil_[2];
                ldsm_x2t(vrh_, sb + VSM(0) + va + nb * 16);
                ldsm_x2t(vrl_, sb + VSM(1) + va + nb * 16);
                ldsm_x2t(vih_, sb + VSM(2) + va + nb * 16);
                ldsm_x2t(vil_, sb + VSM(3) + va + nb * 16);
                mma_f16(Or[nb], Pf[kc], vrh_); mma_f16(Oi[nb], Pf[kc], vih_);
                mma_f16(Or[nb], Pf[kc], vrl_); mma_f16(Oi[nb], Pf[kc], vil_);
            }
        }
        __syncthreads();

        if (j + 1 < NT) { issueV(j + 1); CP_COMMIT(); }
    }

    // ---- epilogue: reduce l, normalize, write O plain fp16 ----
    l0 += __shfl_xor_sync(0xffffffffu, l0, 1);
    l0 += __shfl_xor_sync(0xffffffffu, l0, 2);
    l1 += __shfl_xor_sync(0xffffffffu, l1, 1);
    l1 += __shfl_xor_sync(0xffffffffu, l1, 2);
    const float inv0 = 1.f / l0, inv1 = 1.f / l1;
    const int b  = bh >> 4;
    const int hh = bh & 15;
    const int r0 = qt * 64 + w * 16 + (L >> 2);
    const size_t base0 = ((size_t)b * SEQ + r0) * DIM + hh * 64;
    const size_t base1 = base0 + (size_t)8 * DIM;
#pragma unroll
    for (int nb = 0; nb < 8; ++nb) {
        const int col = nb * 8 + 2 * (L & 3);
        *(uint32_t*)&g_oarh[base0 + col] = packh(Or[nb][0] * inv0, Or[nb][1] * inv0);
        *(uint32_t*)&g_oaih[base0 + col] = packh(Oi[nb][0] * inv0, Oi[nb][1] * inv0);
        *(uint32_t*)&g_oarh[base1 + col] = packh(Or[nb][2] * inv1, Or[nb][3] * inv1);
        *(uint32_t*)&g_oaih[base1 + col] = packh(Oi[nb][2] * inv1, Oi[nb][3] * inv1);
    }
}

// ============================================================
extern "C" void kernel_launch(void* const* d_in, const int* in_sizes, int n_in,
                              void* d_out, int out_size)
{
    const float* x_r    = (const float*)d_in[0];
    const float* x_i    = (const float*)d_in[1];
    const float* Wqkv_r = (const float*)d_in[2];
    const float* bqkv_r = (const float*)d_in[3];
    const float* Wqkv_i = (const float*)d_in[4];
    const float* bqkv_i = (const float*)d_in[5];
    const float* Wout_r = (const float*)d_in[6];
    const float* bout_r = (const float*)d_in[7];
    const float* Wout_i = (const float*)d_in[8];
    const float* bout_i = (const float*)d_in[9];

    cudaFuncSetAttribute(gemm_f16<1>, cudaFuncAttributeMaxDynamicSharedMemorySize, GEMM_SMEM);
    cudaFuncSetAttribute(gemm_f16<0>, cudaFuncAttributeMaxDynamicSharedMemorySize, GEMM_SMEM);
    cudaFuncSetAttribute(attn_mma,    cudaFuncAttributeMaxDynamicSharedMemorySize, ATT_SMEM);

    // 1) fused conversions
    split_all<<<2048, 256>>>(x_r, x_i, Wqkv_r, Wqkv_i, Wout_r, Wout_i);

    // 2) QKV projections (real + imag in one launch)
    dim3 gq(QKV_N / 128, M_TOTAL / 128, 2);    // (24, 32, 2)
    gemm_f16<1><<<gq, 256, GEMM_SMEM>>>(bqkv_r, bqkv_i, nullptr, nullptr);

    // 3) HMMA flash complex attention
    dim3 ga(SEQ / 64, BH);                     // (32, 32)
    attn_mma<<<ga, 128, ATT_SMEM>>>();

    // 4) output projections (real + imag in one launch)
    float* outr = (float*)d_out;
    float* outi = outr + (size_t)OUT_ELEMS;
    dim3 go(DIM / 128, M_TOTAL / 128, 2);      // (8, 32, 2)
    gemm_f16<0><<<go, 256, GEMM_SMEM>>>(bout_r, bout_i, outr, outi);
}

// round 11
// speedup vs baseline: 1.5412x; 1.0033x over previous
#include <cuda_runtime.h>
#include <cuda_fp16.h>
#include <cstdint>
#include <math.h>

#define B_SZ   2
#define SEQ    2048
#define DIM    1024
#define HEADS  16
#define HD     64
#define SCALE  0.125f
#define EXP_C  0.1803368801111243f   /* SCALE * log2(e) */
#define PBIAS  4.0f                  /* p' = 2^(C*mag - PBIAS), cancels in O/l */
#define M_TOTAL (B_SZ * SEQ)
#define QKV_N   (3 * DIM)
#define OUT_ELEMS  (B_SZ * SEQ * DIM)
#define BH      (B_SZ * HEADS)
#define PACKED_ELEMS (BH * SEQ * 128)
#define V_ELEMS      (BH * SEQ * HD)

// ---------------- scratch (static device globals, fp16) ----------------
__device__ __half g_xrh[OUT_ELEMS], g_xih[OUT_ELEMS];                  // x plain
__device__ __half g_wqrh[QKV_N * DIM], g_wqrl[QKV_N * DIM];            // Wqkv hi/lo
__device__ __half g_wqih[QKV_N * DIM], g_wqil[QKV_N * DIM];
__device__ __half g_worh[DIM * DIM], g_worl[DIM * DIM];                // Wout hi/lo
__device__ __half g_woih[DIM * DIM], g_woil[DIM * DIM];
__device__ __half g_qph[PACKED_ELEMS], g_qpl[PACKED_ELEMS];            // Q hi/lo packed
__device__ __half g_kph[PACKED_ELEMS];                                 // K plain packed
__device__ __half g_vrh[V_ELEMS], g_vrl[V_ELEMS];                      // V hi/lo
__device__ __half g_vih[V_ELEMS], g_vil[V_ELEMS];
__device__ __half g_oarh[OUT_ELEMS], g_oaih[OUT_ELEMS];                // O plain

// ---------------- helpers ----------------
__device__ __forceinline__ uint32_t smem_u32(const void* p) {
    uint32_t a;
    asm("{ .reg .u64 t; cvta.to.shared.u64 t, %1; cvt.u32.u64 %0, t; }" : "=r"(a) : "l"(p));
    return a;
}
__device__ __forceinline__ void cp_async16(uint32_t dst, const void* src) {
    asm volatile("cp.async.cg.shared.global [%0], [%1], 16;" :: "r"(dst), "l"(src) : "memory");
}
#define CP_COMMIT()  asm volatile("cp.async.commit_group;" ::: "memory")
#define CP_WAIT0()   asm volatile("cp.async.wait_group 0;" ::: "memory")
#define CP_WAIT1()   asm volatile("cp.async.wait_group 1;" ::: "memory")

__device__ __forceinline__ void mma_f16(float c[4], const uint32_t a[4], const uint32_t b[2]) {
    asm("mma.sync.aligned.m16n8k16.row.col.f32.f16.f16.f32 "
        "{%0,%1,%2,%3}, {%4,%5,%6,%7}, {%8,%9}, {%0,%1,%2,%3};"
        : "+f"(c[0]), "+f"(c[1]), "+f"(c[2]), "+f"(c[3])
        : "r"(a[0]), "r"(a[1]), "r"(a[2]), "r"(a[3]), "r"(b[0]), "r"(b[1]));
}
__device__ __forceinline__ void ldsm_x4(uint32_t r[4], uint32_t a) {
    asm volatile("ldmatrix.sync.aligned.m8n8.x4.shared.b16 {%0,%1,%2,%3}, [%4];"
                 : "=r"(r[0]), "=r"(r[1]), "=r"(r[2]), "=r"(r[3]) : "r"(a));
}
__device__ __forceinline__ void ldsm_x2(uint32_t r[2], uint32_t a) {
    asm volatile("ldmatrix.sync.aligned.m8n8.x2.shared.b16 {%0,%1}, [%2];"
                 : "=r"(r[0]), "=r"(r[1]) : "r"(a));
}
__device__ __forceinline__ void ldsm_x2t(uint32_t r[2], uint32_t a) {
    asm volatile("ldmatrix.sync.aligned.m8n8.x2.trans.shared.b16 {%0,%1}, [%2];"
                 : "=r"(r[0]), "=r"(r[1]) : "r"(a));
}
__device__ __forceinline__ uint32_t packh(float a, float b) {
    __half2 h = __floats2half2_rn(a, b);
    return *reinterpret_cast<uint32_t*>(&h);
}
__device__ __forceinline__ void split2h(float a, float b, uint32_t& hp, uint32_t& lp) {
    __half2 h = __floats2half2_rn(a, b);
    hp = *reinterpret_cast<uint32_t*>(&h);
    const float ra = a - __half2float(__low2half(h));
    const float rb = b - __half2float(__high2half(h));
    __half2 l = __floats2half2_rn(ra, rb);
    lp = *reinterpret_cast<uint32_t*>(&l);
}
__device__ __forceinline__ float ex2f(float x) {
    float r; asm("ex2.approx.f32 %0, %1;" : "=f"(r) : "f"(x)); return r;
}

// ---------------- fused fp32 -> fp16 conversions (one launch) ----------------
#define N_X4   1048576
#define N_WQ4  786432
#define N_WO4  262144
#define SPLIT_TOTAL (2 * N_X4 + 2 * N_WQ4 + 2 * N_WO4)

__global__ void split_all(const float* __restrict__ x_r, const float* __restrict__ x_i,
                          const float* __restrict__ wq_r, const float* __restrict__ wq_i,
                          const float* __restrict__ wo_r, const float* __restrict__ wo_i)
{
    for (int i = blockIdx.x * blockDim.x + threadIdx.x; i < SPLIT_TOTAL;
         i += gridDim.x * blockDim.x) {
        if (i < 2 * N_X4) {                 // x: plain fp16
            const float* src = (i < N_X4) ? x_r : x_i;
            __half* hi = (i < N_X4) ? g_xrh : g_xih;
            const int off = (i < N_X4) ? i : i - N_X4;
            float4 v = ((const float4*)src)[off];
            uint2 hp;
            hp.x = packh(v.x, v.y); hp.y = packh(v.z, v.w);
            ((uint2*)hi)[off] = hp;
        } else {                            // weights: hi/lo
            const float* src; __half *hi, *lo; int off;
            if (i < 2 * N_X4 + 2 * N_WQ4) {
                const int k = i - 2 * N_X4;
                if (k < N_WQ4) { src = wq_r; hi = g_wqrh; lo = g_wqrl; off = k; }
                else           { src = wq_i; hi = g_wqih; lo = g_wqil; off = k - N_WQ4; }
            } else {
                const int k = i - 2 * N_X4 - 2 * N_WQ4;
                if (k < N_WO4) { src = wo_r; hi = g_worh; lo = g_worl; off = k; }
                else           { src = wo_i; hi = g_woih; lo = g_woil; off = k - N_WO4; }
            }
            float4 v = ((const float4*)src)[off];
            uint2 hp, lp;
            split2h(v.x, v.y, hp.x, lp.x);
            split2h(v.z, v.w, hp.y, lp.y);
            ((uint2*)hi)[off] = hp;
            ((uint2*)lo)[off] = lp;
        }
    }
}

// ============================================================
// HMMA fp16 2-term GEMM: D = A @ (Bh+Bl)^T + bias.
// 3-stage cp.async pipeline, ONE barrier per K-chunk.
// CTA 128x128, K-chunk 32, 8 warps (2x4), 2 CTA/SM.
// ============================================================
#define T128_B 10240                   /* 128 rows x 80 B */
#define STG_B  (3 * T128_B)            /* A, Bh, Bl       */
#define GEMM_SMEM (3 * STG_B)          /* 92160           */
#define NCHUNK 32

template<int QKV>
__global__ __launch_bounds__(256, 2)
void gemm_f16(const float* __restrict__ bias_r, const float* __restrict__ bias_i,
              float* __restrict__ Yr, float* __restrict__ Yi)
{
    extern __shared__ char smc[];
    const uint32_t sb = smem_u32(smc);
    const int tid = threadIdx.x;
    const int wid = tid >> 5, lid = tid & 31;
    const int wm = wid >> 2, wn = wid & 3;       // 2 x 4 warp grid
    const int g = lid >> 2, tig = lid & 3;
    const int n0 = blockIdx.x * 128;
    const int m0 = blockIdx.y * 128;
    const int z  = blockIdx.z;

    const __half *A, *Bh, *Bl;
    const float* bias;
    if (QKV) {
        if (z == 0) { A = g_xrh;  Bh = g_wqrh; Bl = g_wqrl; bias = bias_r; }
        else        { A = g_xih;  Bh = g_wqih; Bl = g_wqil; bias = bias_i; }
    } else {
        if (z == 0) { A = g_oarh; Bh = g_worh; Bl = g_worl; bias = bias_r; }
        else        { A = g_oaih; Bh = g_woih; Bl = g_woil; bias = bias_i; }
    }
    float* Y = (z == 0) ? Yr : Yi;

    auto issue_cp = [&](int chunk, int s) {
        const int k0 = chunk * 32;
        const uint32_t base = sb + (uint32_t)s * STG_B;
#pragma unroll
        for (int i = 0; i < 6; ++i) {
            const int lin = tid + i * 256;           // 0..1535
            if (lin < 512) {                          // A
                const int row = lin >> 2, c = lin & 3;
                cp_async16(base + row * 80 + c * 16,
                           A + (size_t)(m0 + row) * DIM + k0 + c * 8);
            } else {                                  // Bh / Bl
                const int l2 = lin - 512;
                const int hl = l2 >> 9, rc = l2 & 511;
                const int row = rc >> 2, c = rc & 3;
                cp_async16(base + T128_B + hl * T128_B + row * 80 + c * 16,
                           (hl ? Bl : Bh) + (size_t)(n0 + row) * DIM + k0 + c * 8);
            }
        }
    };

    const uint32_t a_rel = (uint32_t)((wm * 64 + (lid & 15)) * 80 + ((lid >> 4) << 4));
    const uint32_t b_rel = (uint32_t)((wn * 32 + (lid & 7) + ((lid & 16) >> 1)) * 80 +
                                      ((lid & 8) << 1));

    float acc[4][4][4];
#pragma unroll
    for (int a = 0; a < 4; a++)
#pragma unroll
        for (int b = 0; b < 4; b++)
#pragma unroll
            for (int c = 0; c < 4; c++) acc[a][b][c] = 0.f;

    // prologue: stages 0 and 1 in flight
    issue_cp(0, 0); CP_COMMIT();
    issue_cp(1, 1); CP_COMMIT();

    int stage = 0;
    for (int j = 0; j < NCHUNK; ++j) {
        if (j + 1 < NCHUNK) { CP_WAIT1(); } else { CP_WAIT0(); }
        __syncthreads();                          // chunk j ready; stage (j+2)%3 free
        if (j + 2 < NCHUNK) {
            issue_cp(j + 2, (stage + 2 >= 3) ? stage - 1 : stage + 2);
            CP_COMMIT();
        }

        const uint32_t st  = sb + (uint32_t)stage * STG_B;
        const uint32_t aA  = st + a_rel;
        const uint32_t aBh = st + T128_B + b_rel;
        const uint32_t aBl = aBh + T128_B;

#pragma unroll
        for (int ks = 0; ks < 2; ++ks) {
            uint32_t bh01[4], bh23[4], bl01[4], bl23[4];
            ldsm_x4(bh01, aBh + ks * 32);
            ldsm_x4(bh23, aBh + 1280 + ks * 32);
            ldsm_x4(bl01, aBl + ks * 32);
            ldsm_x4(bl23, aBl + 1280 + ks * 32);
#pragma unroll
            for (int mi = 0; mi < 4; ++mi) {
                uint32_t ah[4];
                ldsm_x4(ah, aA + mi * 1280 + ks * 32);
                mma_f16(acc[mi][0], ah, bh01);
                mma_f16(acc[mi][1], ah, bh01 + 2);
                mma_f16(acc[mi][2], ah, bh23);
                mma_f16(acc[mi][3], ah, bh23 + 2);
                mma_f16(acc[mi][0], ah, bl01);
                mma_f16(acc[mi][1], ah, bl01 + 2);
                mma_f16(acc[mi][2], ah, bl23);
                mma_f16(acc[mi][3], ah, bl23 + 2);
            }
        }
        stage = (stage + 1 == 3) ? 0 : stage + 1;
    }

    // ---- epilogue ----
#pragma unroll
    for (int nb = 0; nb < 4; ++nb) {
        const int n = n0 + wn * 32 + nb * 8 + tig * 2;
        const float b0v = bias[n], b1v = bias[n + 1];
#pragma unroll
        for (int mi = 0; mi < 4; ++mi) {
            const int mlo = m0 + wm * 64 + mi * 16 + g;
#pragma unroll
            for (int half = 0; half < 2; ++half) {
                const int m = mlo + half * 8;
                const float y0 = acc[mi][nb][half * 2 + 0] + b0v;
                const float y1 = acc[mi][nb][half * 2 + 1] + b1v;
                if (!QKV) {
                    *(float2*)&Y[(size_t)m * DIM + n] = make_float2(y0, y1);
                } else {
                    const int which = n >> 10;
                    const int h = (n >> 6) & 15;
                    const int d = n & 63;
                    const int bh = (m >> 11) * HEADS + h;
                    const int ns = m & 2047;
                    if (which == 2) {                  // V: hi/lo
                        uint32_t hp, lp;
                        split2h(y0, y1, hp, lp);
                        const size_t idx = ((size_t)bh * SEQ + ns) * HD + d;
                        if (z == 0) {
                            *(uint32_t*)&g_vrh[idx] = hp;
                            *(uint32_t*)&g_vrl[idx] = lp;
                        } else {
                            *(uint32_t*)&g_vih[idx] = hp;
                            *(uint32_t*)&g_vil[idx] = lp;
                        }
                    } else {
                        const size_t idx = ((size_t)bh * SEQ + ns) * 128 + d + (z ? 64 : 0);
                        if (which == 0) {              // Q: hi/lo
                            uint32_t hp, lp;
                            split2h(y0, y1, hp, lp);
                            *(uint32_t*)&g_qph[idx] = hp;
                            *(uint32_t*)&g_qpl[idx] = lp;
                        } else {                       // K: plain
                            *(uint32_t*)&g_kph[idx] = packh(y0, y1);
                        }
                    }
                }
            }
        }
    }
}

// ============================================================
// HMMA flash complex attention (unchanged from Round 10).
// ============================================================
#define NT 32
#define QSM_H 0u
#define QSM_L 17408u
#define KSM   34816u
#define VSM(b) (52224u + (uint32_t)(b) * 9216u)
#define ATT_SMEM 89088

__global__ __launch_bounds__(128, 2)
void attn_mma()
{
    extern __shared__ char smb[];
    const uint32_t sb = smem_u32(smb);
    const int tid = threadIdx.x, w = tid >> 5, L = tid & 31;
    const int bh = blockIdx.y, qt = blockIdx.x;
    const size_t kvrow0 = (size_t)bh * SEQ;

    auto issueQ = [&]() {
        const size_t qb = (kvrow0 + (size_t)qt * 64) * 128;
#pragma unroll
        for (int i = 0; i < 16; ++i) {
            const int lin = tid + i * 128;
            const int hl = lin >> 10, rem = lin & 1023, row = rem >> 4, ch = rem & 15;
            const __half* src = (hl ? g_qpl : g_qph) + qb + row * 128 + ch * 8;
            cp_async16(sb + (hl ? QSM_L : QSM_H) + row * 272 + ch * 16, src);
        }
    };
    auto issueK = [&](int kt) {
#pragma unroll
        for (int i = 0; i < 8; ++i) {
            const int lin = tid + i * 128;
            const int row = lin >> 4, ch = lin & 15;
            cp_async16(sb + KSM + row * 272 + ch * 16,
                       g_kph + (kvrow0 + kt * 64 + row) * 128 + ch * 8);
        }
    };
    auto issueV = [&](int kt) {
        const __half* bufs[4] = { g_vrh, g_vrl, g_vih, g_vil };
#pragma unroll
        for (int i = 0; i < 16; ++i) {
            const int lin = tid + i * 128;
            const int bf = lin >> 9, rem = lin & 511, row = rem >> 3, ch = rem & 7;
            cp_async16(sb + VSM(bf) + row * 144 + ch * 16,
                       bufs[bf] + (kvrow0 + kt * 64 + row) * HD + ch * 8);
        }
    };

    float Or[8][4], Oi[8][4];
#pragma unroll
    for (int nb = 0; nb < 8; ++nb)
#pragma unroll
        for (int e = 0; e < 4; ++e) { Or[nb][e] = 0.f; Oi[nb][e] = 0.f; }
    float l0 = 0.f, l1 = 0.f;

    const uint32_t a_off = (uint32_t)((w * 16 + (L & 7) + (L & 8)) * 272 + ((L & 16) ? 16 : 0));
    const uint32_t brow  = (uint32_t)((L & 7) * 272 + ((L & 8) ? 16 : 0));
    const uint32_t vrow  = (uint32_t)(((L & 7) + (L & 8)) * 144);

    issueQ(); issueK(0); CP_COMMIT();
    issueV(0); CP_COMMIT();

    for (int j = 0; j < NT; ++j) {
        CP_WAIT1();
        __syncthreads();

        float Sr[8][4], Si[8][4];
#pragma unroll
        for (int nb = 0; nb < 8; ++nb)
#pragma unroll
            for (int e = 0; e < 4; ++e) { Sr[nb][e] = 0.f; Si[nb][e] = 0.f; }

#pragma unroll
        for (int c = 0; c < 4; ++c) {
            uint32_t fh[4], fl[4], gh[4], gl[4], nh[4], nl[4];
            ldsm_x4(fh, sb + QSM_H + a_off + c * 32);
            ldsm_x4(fl, sb + QSM_L + a_off + c * 32);
            ldsm_x4(gh, sb + QSM_H + a_off + (c + 4) * 32);
            ldsm_x4(gl, sb + QSM_L + a_off + (c + 4) * 32);
#pragma unroll
            for (int r = 0; r < 4; ++r) { nh[r] = fh[r] ^ 0x80008000u; nl[r] = fl[r] ^ 0x80008000u; }
#pragma unroll
            for (int nb = 0; nb < 8; ++nb) {
                const uint32_t ba = (uint32_t)nb * 2176u + brow;
                uint32_t bc[2], bd[2];
                ldsm_x2(bc, sb + KSM + ba + c * 32);
                ldsm_x2(bd, sb + KSM + ba + (c + 4) * 32);
                mma_f16(Sr[nb], fh, bc); mma_f16(Si[nb], gh, bc);
                mma_f16(Sr[nb], fl, bc); mma_f16(Si[nb], gl, bc);
                mma_f16(Sr[nb], gh, bd); mma_f16(Si[nb], nh, bd);
                mma_f16(Sr[nb], gl, bd); mma_f16(Si[nb], nl, bd);
            }
        }
        __syncthreads();

        if (j + 1 < NT) { issueK(j + 1); CP_COMMIT(); }

#pragma unroll
        for (int nb = 0; nb < 8; ++nb)
#pragma unroll
            for (int e = 0; e < 4; ++e) {
                const float x = fmaf(Sr[nb][e], Sr[nb][e], Si[nb][e] * Si[nb][e]);
                float rs; asm("rsqrt.approx.f32 %0, %1;" : "=f"(rs) : "f"(x + 1e-30f));
                const float p = ex2f((EXP_C * x) * rs - PBIAS);
                Sr[nb][e] = p;
                if (e < 2) l0 += p; else l1 += p;
            }

        uint32_t Pf[4][4];
#pragma unroll
        for (int kc = 0; kc < 4; ++kc) {
            Pf[kc][0] = packh(Sr[2 * kc][0],     Sr[2 * kc][1]);
            Pf[kc][1] = packh(Sr[2 * kc][2],     Sr[2 * kc][3]);
            Pf[kc][2] = packh(Sr[2 * kc + 1][0], Sr[2 * kc + 1][1]);
            Pf[kc][3] = packh(Sr[2 * kc + 1][2], Sr[2 * kc + 1][3]);
        }

        if (j + 1 < NT) { CP_WAIT1(); } else { CP_WAIT0(); }
        __syncthreads();

#pragma unroll
        for (int kc = 0; kc < 4; ++kc) {
            const uint32_t va = vrow + (uint32_t)kc * 2304u;
#pragma unroll
            for (int nb = 0; nb < 8; ++nb) {
                uint32_t vrh_[2], vrl_[2], vih_[2], vil_[2];
                ldsm_x2t(vrh_, sb + VSM(0) + va + nb * 16);
                ldsm_x2t(vrl_, sb + VSM(1) + va + nb * 16);
                ldsm_x2t(vih_, sb + VSM(2) + va + nb * 16);
                ldsm_x2t(vil_, sb + VSM(3) + va + nb * 16);
                mma_f16(Or[nb], Pf[kc], vrh_); mma_f16(Oi[nb], Pf[kc], vih_);
                mma_f16(Or[nb], Pf[kc], vrl_); mma_f16(Oi[nb], Pf[kc], vil_);
            }
        }
        __syncthreads();

        if (j + 1 < NT) { issueV(j + 1); CP_COMMIT(); }
    }

    l0 += __shfl_xor_sync(0xffffffffu, l0, 1);
    l0 += __shfl_xor_sync(0xffffffffu, l0, 2);
    l1 += __shfl_xor_sync(0xffffffffu, l1, 1);
    l1 += __shfl_xor_sync(0xffffffffu, l1, 2);
    const float inv0 = 1.f / l0, inv1 = 1.f / l1;
    const int b  = bh >> 4;
    const int hh = bh & 15;
    const int r0 = qt * 64 + w * 16 + (L >> 2);
    const size_t base0 = ((size_t)b * SEQ + r0) * DIM + hh * 64;
    const size_t base1 = base0 + (size_t)8 * DIM;
#pragma unroll
    for (int nb = 0; nb < 8; ++nb) {
        const int col = nb * 8 + 2 * (L & 3);
        *(uint32_t*)&g_oarh[base0 + col] = packh(Or[nb][0] * inv0, Or[nb][1] * inv0);
        *(uint32_t*)&g_oaih[base0 + col] = packh(Oi[nb][0] * inv0, Oi[nb][1] * inv0);
        *(uint32_t*)&g_oarh[base1 + col] = packh(Or[nb][2] * inv1, Or[nb][3] * inv1);
        *(uint32_t*)&g_oaih[base1 + col] = packh(Oi[nb][2] * inv1, Oi[nb][3] * inv1);
    }
}

// ============================================================
extern "C" void kernel_launch(void* const* d_in, const int* in_sizes, int n_in,
                              void* d_out, int out_size)
{
    const float* x_r    = (const float*)d_in[0];
    const float* x_i    = (const float*)d_in[1];
    const float* Wqkv_r = (const float*)d_in[2];
    const float* bqkv_r = (const float*)d_in[3];
    const float* Wqkv_i = (const float*)d_in[4];
    const float* bqkv_i = (const float*)d_in[5];
    const float* Wout_r = (const float*)d_in[6];
    const float* bout_r = (const float*)d_in[7];
    const float* Wout_i = (const float*)d_in[8];
    const float* bout_i = (const float*)d_in[9];

    cudaFuncSetAttribute(gemm_f16<1>, cudaFuncAttributeMaxDynamicSharedMemorySize, GEMM_SMEM);
    cudaFuncSetAttribute(gemm_f16<0>, cudaFuncAttributeMaxDynamicSharedMemorySize, GEMM_SMEM);
    cudaFuncSetAttribute(attn_mma,    cudaFuncAttributeMaxDynamicSharedMemorySize, ATT_SMEM);

    // 1) fused conversions
    split_all<<<2048, 256>>>(x_r, x_i, Wqkv_r, Wqkv_i, Wout_r, Wout_i);

    // 2) QKV projections (real + imag in one launch)
    dim3 gq(QKV_N / 128, M_TOTAL / 128, 2);    // (24, 32, 2)
    gemm_f16<1><<<gq, 256, GEMM_SMEM>>>(bqkv_r, bqkv_i, nullptr, nullptr);

    // 3) HMMA flash complex attention
    dim3 ga(SEQ / 64, BH);                     // (32, 32)
    attn_mma<<<ga, 128, ATT_SMEM>>>();

    // 4) output projections (real + imag in one launch)
    float* outr = (float*)d_out;
    float* outi = outr + (size_t)OUT_ELEMS;
    dim3 go(DIM / 128, M_TOTAL / 128, 2);      // (8, 32, 2)
    gemm_f16<0><<<go, 256, GEMM_SMEM>>>(bout_r, bout_i, outr, outi);
}

// round 12
// speedup vs baseline: 1.7567x; 1.1398x over previous
#include <cuda_runtime.h>
#include <cuda_fp16.h>
#include <cstdint>
#include <math.h>

#define B_SZ   2
#define SEQ    2048
#define DIM    1024
#define HEADS  16
#define HD     64
#define SCALE  0.125f
#define EXP_C  0.1803368801111243f   /* SCALE * log2(e) */
#define PBIAS  4.0f
#define M_TOTAL (B_SZ * SEQ)
#define QKV_N   (3 * DIM)
#define OUT_ELEMS  (B_SZ * SEQ * DIM)
#define BH      (B_SZ * HEADS)
#define PACKED_ELEMS (BH * SEQ * 128)
#define V_ELEMS      (BH * SEQ * HD)

// ---------------- scratch (static device globals, fp16) ----------------
__device__ __half g_xrh[OUT_ELEMS], g_xih[OUT_ELEMS];                  // x plain
__device__ __half g_wqrh[QKV_N * DIM], g_wqrl[QKV_N * DIM];            // Wqkv hi/lo
__device__ __half g_wqih[QKV_N * DIM], g_wqil[QKV_N * DIM];
__device__ __half g_worh[DIM * DIM], g_worl[DIM * DIM];                // Wout hi/lo
__device__ __half g_woih[DIM * DIM], g_woil[DIM * DIM];
__device__ __half g_qph[PACKED_ELEMS];                                 // Q plain packed
__device__ __half g_kph[PACKED_ELEMS];                                 // K plain packed
__device__ __half g_vrh[V_ELEMS], g_vrl[V_ELEMS];                      // V hi/lo
__device__ __half g_vih[V_ELEMS], g_vil[V_ELEMS];
__device__ __half g_oarh[OUT_ELEMS], g_oaih[OUT_ELEMS];                // O plain

// ---------------- helpers ----------------
__device__ __forceinline__ uint32_t smem_u32(const void* p) {
    uint32_t a;
    asm("{ .reg .u64 t; cvta.to.shared.u64 t, %1; cvt.u32.u64 %0, t; }" : "=r"(a) : "l"(p));
    return a;
}
__device__ __forceinline__ void cp_async16(uint32_t dst, const void* src) {
    asm volatile("cp.async.cg.shared.global [%0], [%1], 16;" :: "r"(dst), "l"(src) : "memory");
}
#define CP_COMMIT()  asm volatile("cp.async.commit_group;" ::: "memory")
#define CP_WAIT0()   asm volatile("cp.async.wait_group 0;" ::: "memory")
#define CP_WAIT1()   asm volatile("cp.async.wait_group 1;" ::: "memory")

__device__ __forceinline__ void mma_f16(float c[4], const uint32_t a[4], const uint32_t b[2]) {
    asm("mma.sync.aligned.m16n8k16.row.col.f32.f16.f16.f32 "
        "{%0,%1,%2,%3}, {%4,%5,%6,%7}, {%8,%9}, {%0,%1,%2,%3};"
        : "+f"(c[0]), "+f"(c[1]), "+f"(c[2]), "+f"(c[3])
        : "r"(a[0]), "r"(a[1]), "r"(a[2]), "r"(a[3]), "r"(b[0]), "r"(b[1]));
}
__device__ __forceinline__ void ldsm_x4(uint32_t r[4], uint32_t a) {
    asm volatile("ldmatrix.sync.aligned.m8n8.x4.shared.b16 {%0,%1,%2,%3}, [%4];"
                 : "=r"(r[0]), "=r"(r[1]), "=r"(r[2]), "=r"(r[3]) : "r"(a));
}
__device__ __forceinline__ void ldsm_x2(uint32_t r[2], uint32_t a) {
    asm volatile("ldmatrix.sync.aligned.m8n8.x2.shared.b16 {%0,%1}, [%2];"
                 : "=r"(r[0]), "=r"(r[1]) : "r"(a));
}
__device__ __forceinline__ void ldsm_x2t(uint32_t r[2], uint32_t a) {
    asm volatile("ldmatrix.sync.aligned.m8n8.x2.trans.shared.b16 {%0,%1}, [%2];"
                 : "=r"(r[0]), "=r"(r[1]) : "r"(a));
}
__device__ __forceinline__ uint32_t packh(float a, float b) {
    __half2 h = __floats2half2_rn(a, b);
    return *reinterpret_cast<uint32_t*>(&h);
}
__device__ __forceinline__ void split2h(float a, float b, uint32_t& hp, uint32_t& lp) {
    __half2 h = __floats2half2_rn(a, b);
    hp = *reinterpret_cast<uint32_t*>(&h);
    const float ra = a - __half2float(__low2half(h));
    const float rb = b - __half2float(__high2half(h));
    __half2 l = __floats2half2_rn(ra, rb);
    lp = *reinterpret_cast<uint32_t*>(&l);
}
__device__ __forceinline__ float ex2f(float x) {
    float r; asm("ex2.approx.f32 %0, %1;" : "=f"(r) : "f"(x)); return r;
}

// ---------------- fused fp32 -> fp16 conversions (one launch) ----------------
#define N_X4   1048576
#define N_WQ4  786432
#define N_WO4  262144
#define SPLIT_TOTAL (2 * N_X4 + 2 * N_WQ4 + 2 * N_WO4)

__global__ void split_all(const float* __restrict__ x_r, const float* __restrict__ x_i,
                          const float* __restrict__ wq_r, const float* __restrict__ wq_i,
                          const float* __restrict__ wo_r, const float* __restrict__ wo_i)
{
    for (int i = blockIdx.x * blockDim.x + threadIdx.x; i < SPLIT_TOTAL;
         i += gridDim.x * blockDim.x) {
        if (i < 2 * N_X4) {                 // x: plain fp16
            const float* src = (i < N_X4) ? x_r : x_i;
            __half* hi = (i < N_X4) ? g_xrh : g_xih;
            const int off = (i < N_X4) ? i : i - N_X4;
            float4 v = ((const float4*)src)[off];
            uint2 hp;
            hp.x = packh(v.x, v.y); hp.y = packh(v.z, v.w);
            ((uint2*)hi)[off] = hp;
        } else {                            // weights: hi/lo
            const float* src; __half *hi, *lo; int off;
            if (i < 2 * N_X4 + 2 * N_WQ4) {
                const int k = i - 2 * N_X4;
                if (k < N_WQ4) { src = wq_r; hi = g_wqrh; lo = g_wqrl; off = k; }
                else           { src = wq_i; hi = g_wqih; lo = g_wqil; off = k - N_WQ4; }
            } else {
                const int k = i - 2 * N_X4 - 2 * N_WQ4;
                if (k < N_WO4) { src = wo_r; hi = g_worh; lo = g_worl; off = k; }
                else           { src = wo_i; hi = g_woih; lo = g_woil; off = k - N_WO4; }
            }
            float4 v = ((const float4*)src)[off];
            uint2 hp, lp;
            split2h(v.x, v.y, hp.x, lp.x);
            split2h(v.z, v.w, hp.y, lp.y);
            ((uint2*)hi)[off] = hp;
            ((uint2*)lo)[off] = lp;
        }
    }
}

// ============================================================
// HMMA fp16 2-term GEMM (unchanged from Round 11 except Q-plain
// epilogue): D = A @ (Bh+Bl)^T + bias.
// ============================================================
#define T128_B 10240
#define STG_B  (3 * T128_B)
#define GEMM_SMEM (3 * STG_B)
#define NCHUNK 32

template<int QKV>
__global__ __launch_bounds__(256, 2)
void gemm_f16(const float* __restrict__ bias_r, const float* __restrict__ bias_i,
              float* __restrict__ Yr, float* __restrict__ Yi)
{
    extern __shared__ char smc[];
    const uint32_t sb = smem_u32(smc);
    const int tid = threadIdx.x;
    const int wid = tid >> 5, lid = tid & 31;
    const int wm = wid >> 2, wn = wid & 3;
    const int g = lid >> 2, tig = lid & 3;
    const int n0 = blockIdx.x * 128;
    const int m0 = blockIdx.y * 128;
    const int z  = blockIdx.z;

    const __half *A, *Bh, *Bl;
    const float* bias;
    if (QKV) {
        if (z == 0) { A = g_xrh;  Bh = g_wqrh; Bl = g_wqrl; bias = bias_r; }
        else        { A = g_xih;  Bh = g_wqih; Bl = g_wqil; bias = bias_i; }
    } else {
        if (z == 0) { A = g_oarh; Bh = g_worh; Bl = g_worl; bias = bias_r; }
        else        { A = g_oaih; Bh = g_woih; Bl = g_woil; bias = bias_i; }
    }
    float* Y = (z == 0) ? Yr : Yi;

    auto issue_cp = [&](int chunk, int s) {
        const int k0 = chunk * 32;
        const uint32_t base = sb + (uint32_t)s * STG_B;
#pragma unroll
        for (int i = 0; i < 6; ++i) {
            const int lin = tid + i * 256;
            if (lin < 512) {
                const int row = lin >> 2, c = lin & 3;
                cp_async16(base + row * 80 + c * 16,
                           A + (size_t)(m0 + row) * DIM + k0 + c * 8);
            } else {
                const int l2 = lin - 512;
                const int hl = l2 >> 9, rc = l2 & 511;
                const int row = rc >> 2, c = rc & 3;
                cp_async16(base + T128_B + hl * T128_B + row * 80 + c * 16,
                           (hl ? Bl : Bh) + (size_t)(n0 + row) * DIM + k0 + c * 8);
            }
        }
    };

    const uint32_t a_rel = (uint32_t)((wm * 64 + (lid & 15)) * 80 + ((lid >> 4) << 4));
    const uint32_t b_rel = (uint32_t)((wn * 32 + (lid & 7) + ((lid & 16) >> 1)) * 80 +
                                      ((lid & 8) << 1));

    float acc[4][4][4];
#pragma unroll
    for (int a = 0; a < 4; a++)
#pragma unroll
        for (int b = 0; b < 4; b++)
#pragma unroll
            for (int c = 0; c < 4; c++) acc[a][b][c] = 0.f;

    issue_cp(0, 0); CP_COMMIT();
    issue_cp(1, 1); CP_COMMIT();

    int stage = 0;
    for (int j = 0; j < NCHUNK; ++j) {
        if (j + 1 < NCHUNK) { CP_WAIT1(); } else { CP_WAIT0(); }
        __syncthreads();
        if (j + 2 < NCHUNK) {
            issue_cp(j + 2, (stage + 2 >= 3) ? stage - 1 : stage + 2);
            CP_COMMIT();
        }

        const uint32_t st  = sb + (uint32_t)stage * STG_B;
        const uint32_t aA  = st + a_rel;
        const uint32_t aBh = st + T128_B + b_rel;
        const uint32_t aBl = aBh + T128_B;

#pragma unroll
        for (int ks = 0; ks < 2; ++ks) {
            uint32_t bh01[4], bh23[4], bl01[4], bl23[4];
            ldsm_x4(bh01, aBh + ks * 32);
            ldsm_x4(bh23, aBh + 1280 + ks * 32);
            ldsm_x4(bl01, aBl + ks * 32);
            ldsm_x4(bl23, aBl + 1280 + ks * 32);
#pragma unroll
            for (int mi = 0; mi < 4; ++mi) {
                uint32_t ah[4];
                ldsm_x4(ah, aA + mi * 1280 + ks * 32);
                mma_f16(acc[mi][0], ah, bh01);
                mma_f16(acc[mi][1], ah, bh01 + 2);
                mma_f16(acc[mi][2], ah, bh23);
                mma_f16(acc[mi][3], ah, bh23 + 2);
                mma_f16(acc[mi][0], ah, bl01);
                mma_f16(acc[mi][1], ah, bl01 + 2);
                mma_f16(acc[mi][2], ah, bl23);
                mma_f16(acc[mi][3], ah, bl23 + 2);
            }
        }
        stage = (stage + 1 == 3) ? 0 : stage + 1;
    }

    // ---- epilogue ----
#pragma unroll
    for (int nb = 0; nb < 4; ++nb) {
        const int n = n0 + wn * 32 + nb * 8 + tig * 2;
        const float b0v = bias[n], b1v = bias[n + 1];
#pragma unroll
        for (int mi = 0; mi < 4; ++mi) {
            const int mlo = m0 + wm * 64 + mi * 16 + g;
#pragma unroll
            for (int half = 0; half < 2; ++half) {
                const int m = mlo + half * 8;
                const float y0 = acc[mi][nb][half * 2 + 0] + b0v;
                const float y1 = acc[mi][nb][half * 2 + 1] + b1v;
                if (!QKV) {
                    *(float2*)&Y[(size_t)m * DIM + n] = make_float2(y0, y1);
                } else {
                    const int which = n >> 10;
                    const int h = (n >> 6) & 15;
                    const int d = n & 63;
                    const int bh = (m >> 11) * HEADS + h;
                    const int ns = m & 2047;
                    if (which == 2) {                  // V: hi/lo
                        uint32_t hp, lp;
                        split2h(y0, y1, hp, lp);
                        const size_t idx = ((size_t)bh * SEQ + ns) * HD + d;
                        if (z == 0) {
                            *(uint32_t*)&g_vrh[idx] = hp;
                            *(uint32_t*)&g_vrl[idx] = lp;
                        } else {
                            *(uint32_t*)&g_vih[idx] = hp;
                            *(uint32_t*)&g_vil[idx] = lp;
                        }
                    } else {                           // Q and K: plain
                        const size_t idx = ((size_t)bh * SEQ + ns) * 128 + d + (z ? 64 : 0);
                        const uint32_t hp = packh(y0, y1);
                        if (which == 0) *(uint32_t*)&g_qph[idx] = hp;
                        else            *(uint32_t*)&g_kph[idx] = hp;
                    }
                }
            }
        }
    }
}

// ============================================================
// HMMA flash complex attention: Q plain, K plain, P plain
// (biased), V fp16x2. No-max softmax. 2 CTAs/SM.
// ============================================================
#define NT 32
#define QSM   0u
#define KSM   17408u
#define VSM(b) (34816u + (uint32_t)(b) * 9216u)
#define ATT_SMEM 71680

__global__ __launch_bounds__(128, 2)
void attn_mma()
{
    extern __shared__ char smb[];
    const uint32_t sb = smem_u32(smb);
    const int tid = threadIdx.x, w = tid >> 5, L = tid & 31;
    const int bh = blockIdx.y, qt = blockIdx.x;
    const size_t kvrow0 = (size_t)bh * SEQ;

    auto issueQ = [&]() {
        const size_t qb = (kvrow0 + (size_t)qt * 64) * 128;
#pragma unroll
        for (int i = 0; i < 8; ++i) {
            const int lin = tid + i * 128;
            const int row = lin >> 4, ch = lin & 15;
            cp_async16(sb + QSM + row * 272 + ch * 16, g_qph + qb + row * 128 + ch * 8);
        }
    };
    auto issueK = [&](int kt) {
#pragma unroll
        for (int i = 0; i < 8; ++i) {
            const int lin = tid + i * 128;
            const int row = lin >> 4, ch = lin & 15;
            cp_async16(sb + KSM + row * 272 + ch * 16,
                       g_kph + (kvrow0 + kt * 64 + row) * 128 + ch * 8);
        }
    };
    auto issueV = [&](int kt) {
        const __half* bufs[4] = { g_vrh, g_vrl, g_vih, g_vil };
#pragma unroll
        for (int i = 0; i < 16; ++i) {
            const int lin = tid + i * 128;
            const int bf = lin >> 9, rem = lin & 511, row = rem >> 3, ch = rem & 7;
            cp_async16(sb + VSM(bf) + row * 144 + ch * 16,
                       bufs[bf] + (kvrow0 + kt * 64 + row) * HD + ch * 8);
        }
    };

    float Or[8][4], Oi[8][4];
#pragma unroll
    for (int nb = 0; nb < 8; ++nb)
#pragma unroll
        for (int e = 0; e < 4; ++e) { Or[nb][e] = 0.f; Oi[nb][e] = 0.f; }
    float l0 = 0.f, l1 = 0.f;

    const uint32_t a_off = (uint32_t)((w * 16 + (L & 7) + (L & 8)) * 272 + ((L & 16) ? 16 : 0));
    const uint32_t brow  = (uint32_t)((L & 7) * 272 + ((L & 8) ? 16 : 0));
    const uint32_t vrow  = (uint32_t)(((L & 7) + (L & 8)) * 144);

    issueQ(); issueK(0); CP_COMMIT();
    issueV(0); CP_COMMIT();

    for (int j = 0; j < NT; ++j) {
        CP_WAIT1();
        __syncthreads();

        float Sr[8][4], Si[8][4];
#pragma unroll
        for (int nb = 0; nb < 8; ++nb)
#pragma unroll
            for (int e = 0; e < 4; ++e) { Sr[nb][e] = 0.f; Si[nb][e] = 0.f; }

        // ---- scores: Sr = [Qr|Qi]·K^T, Si = [Qi|-Qr]·K^T (all plain) ----
#pragma unroll
        for (int c = 0; c < 4; ++c) {
            uint32_t fh[4], gh[4], nh[4];
            ldsm_x4(fh, sb + QSM + a_off + c * 32);
            ldsm_x4(gh, sb + QSM + a_off + (c + 4) * 32);
#pragma unroll
            for (int r = 0; r < 4; ++r) nh[r] = fh[r] ^ 0x80008000u;
#pragma unroll
            for (int nb = 0; nb < 8; ++nb) {
                const uint32_t ba = (uint32_t)nb * 2176u + brow;
                uint32_t bc[2], bd[2];
                ldsm_x2(bc, sb + KSM + ba + c * 32);
                ldsm_x2(bd, sb + KSM + ba + (c + 4) * 32);
                mma_f16(Sr[nb], fh, bc); mma_f16(Si[nb], gh, bc);
                mma_f16(Sr[nb], gh, bd); mma_f16(Si[nb], nh, bd);
            }
        }
        __syncthreads();

        if (j + 1 < NT) { issueK(j + 1); CP_COMMIT(); }

        // ---- no-max softmax: p' = 2^(C*mag - PBIAS) ----
#pragma unroll
        for (int nb = 0; nb < 8; ++nb)
#pragma unroll
            for (int e = 0; e < 4; ++e) {
                const float x = fmaf(Sr[nb][e], Sr[nb][e], Si[nb][e] * Si[nb][e]);
                float rs; asm("rsqrt.approx.f32 %0, %1;" : "=f"(rs) : "f"(x + 1e-30f));
                const float p = ex2f((EXP_C * x) * rs - PBIAS);
                Sr[nb][e] = p;
                if (e < 2) l0 += p; else l1 += p;
            }

        // ---- pack P (plain fp16) ----
        uint32_t Pf[4][4];
#pragma unroll
        for (int kc = 0; kc < 4; ++kc) {
            Pf[kc][0] = packh(Sr[2 * kc][0],     Sr[2 * kc][1]);
            Pf[kc][1] = packh(Sr[2 * kc][2],     Sr[2 * kc][3]);
            Pf[kc][2] = packh(Sr[2 * kc + 1][0], Sr[2 * kc + 1][1]);
            Pf[kc][3] = packh(Sr[2 * kc + 1][2], Sr[2 * kc + 1][3]);
        }

        if (j + 1 < NT) { CP_WAIT1(); } else { CP_WAIT0(); }
        __syncthreads();

        // ---- PV: O += P @ (Vh + Vl) ----
#pragma unroll
        for (int kc = 0; kc < 4; ++kc) {
            const uint32_t va = vrow + (uint32_t)kc * 2304u;
#pragma unroll
            for (int nb = 0; nb < 8; ++nb) {
                uint32_t vrh_[2], vrl_[2], vih_[2], vil_[2];
                ldsm_x2t(vrh_, sb + VSM(0) + va + nb * 16);
                ldsm_x2t(vrl_, sb + VSM(1) + va + nb * 16);
                ldsm_x2t(vih_, sb + VSM(2) + va + nb * 16);
                ldsm_x2t(vil_, sb + VSM(3) + va + nb * 16);
                mma_f16(Or[nb], Pf[kc], vrh_); mma_f16(Oi[nb], Pf[kc], vih_);
                mma_f16(Or[nb], Pf[kc], vrl_); mma_f16(Oi[nb], Pf[kc], vil_);
            }
        }
        __syncthreads();

        if (j + 1 < NT) { issueV(j + 1); CP_COMMIT(); }
    }

    // ---- epilogue ----
    l0 += __shfl_xor_sync(0xffffffffu, l0, 1);
    l0 += __shfl_xor_sync(0xffffffffu, l0, 2);
    l1 += __shfl_xor_sync(0xffffffffu, l1, 1);
    l1 += __shfl_xor_sync(0xffffffffu, l1, 2);
    const float inv0 = 1.f / l0, inv1 = 1.f / l1;
    const int b  = bh >> 4;
    const int hh = bh & 15;
    const int r0 = qt * 64 + w * 16 + (L >> 2);
    const size_t base0 = ((size_t)b * SEQ + r0) * DIM + hh * 64;
    const size_t base1 = base0 + (size_t)8 * DIM;
#pragma unroll
    for (int nb = 0; nb < 8; ++nb) {
        const int col = nb * 8 + 2 * (L & 3);
        *(uint32_t*)&g_oarh[base0 + col] = packh(Or[nb][0] * inv0, Or[nb][1] * inv0);
        *(uint32_t*)&g_oaih[base0 + col] = packh(Oi[nb][0] * inv0, Oi[nb][1] * inv0);
        *(uint32_t*)&g_oarh[base1 + col] = packh(Or[nb][2] * inv1, Or[nb][3] * inv1);
        *(uint32_t*)&g_oaih[base1 + col] = packh(Oi[nb][2] * inv1, Oi[nb][3] * inv1);
    }
}

// ============================================================
extern "C" void kernel_launch(void* const* d_in, const int* in_sizes, int n_in,
                              void* d_out, int out_size)
{
    const float* x_r    = (const float*)d_in[0];
    const float* x_i    = (const float*)d_in[1];
    const float* Wqkv_r = (const float*)d_in[2];
    const float* bqkv_r = (const float*)d_in[3];
    const float* Wqkv_i = (const float*)d_in[4];
    const float* bqkv_i = (const float*)d_in[5];
    const float* Wout_r = (const float*)d_in[6];
    const float* bout_r = (const float*)d_in[7];
    const float* Wout_i = (const float*)d_in[8];
    const float* bout_i = (const float*)d_in[9];

    cudaFuncSetAttribute(gemm_f16<1>, cudaFuncAttributeMaxDynamicSharedMemorySize, GEMM_SMEM);
    cudaFuncSetAttribute(gemm_f16<0>, cudaFuncAttributeMaxDynamicSharedMemorySize, GEMM_SMEM);
    cudaFuncSetAttribute(attn_mma,    cudaFuncAttributeMaxDynamicSharedMemorySize, ATT_SMEM);

    // 1) fused conversions
    split_all<<<2048, 256>>>(x_r, x_i, Wqkv_r, Wqkv_i, Wout_r, Wout_i);

    // 2) QKV projections (real + imag in one launch)
    dim3 gq(QKV_N / 128, M_TOTAL / 128, 2);    // (24, 32, 2)
    gemm_f16<1><<<gq, 256, GEMM_SMEM>>>(bqkv_r, bqkv_i, nullptr, nullptr);

    // 3) HMMA flash complex attention
    dim3 ga(SEQ / 64, BH);                     // (32, 32)
    attn_mma<<<ga, 128, ATT_SMEM>>>();

    // 4) output projections (real + imag in one launch)
    float* outr = (float*)d_out;
    float* outi = outr + (size_t)OUT_ELEMS;
    dim3 go(DIM / 128, M_TOTAL / 128, 2);      // (8, 32, 2)
    gemm_f16<0><<<go, 256, GEMM_SMEM>>>(bout_r, bout_i, outr, outi);
}

// round 13
// speedup vs baseline: 1.9590x; 1.1152x over previous
#include <cuda_runtime.h>
#include <cuda_fp16.h>
#include <cstdint>
#include <math.h>

#define B_SZ   2
#define SEQ    2048
#define DIM    1024
#define HEADS  16
#define HD     64
#define SCALE  0.125f
#define EXP_C  0.1803368801111243f   /* SCALE * log2(e) */
#define PBIAS  4.0f
#define M_TOTAL (B_SZ * SEQ)
#define QKV_N   (3 * DIM)
#define OUT_ELEMS  (B_SZ * SEQ * DIM)
#define BH      (B_SZ * HEADS)
#define PACKED_ELEMS (BH * SEQ * 128)
#define V_ELEMS      (BH * SEQ * HD)

// ---------------- scratch (static device globals, fp16) ----------------
__device__ __half g_xrh[OUT_ELEMS], g_xih[OUT_ELEMS];                  // x plain
__device__ __half g_wqrh[QKV_N * DIM], g_wqrl[QKV_N * DIM];            // Wqkv hi/lo
__device__ __half g_wqih[QKV_N * DIM], g_wqil[QKV_N * DIM];
__device__ __half g_worh[DIM * DIM], g_worl[DIM * DIM];                // Wout hi/lo
__device__ __half g_woih[DIM * DIM], g_woil[DIM * DIM];
__device__ __half g_qph[PACKED_ELEMS];                                 // Q plain packed
__device__ __half g_kph[PACKED_ELEMS];                                 // K plain packed
__device__ __half g_vrh[V_ELEMS], g_vih[V_ELEMS];                      // V plain
__device__ __half g_oarh[OUT_ELEMS], g_oaih[OUT_ELEMS];                // O plain

// ---------------- helpers ----------------
__device__ __forceinline__ uint32_t smem_u32(const void* p) {
    uint32_t a;
    asm("{ .reg .u64 t; cvta.to.shared.u64 t, %1; cvt.u32.u64 %0, t; }" : "=r"(a) : "l"(p));
    return a;
}
__device__ __forceinline__ void cp_async16(uint32_t dst, const void* src) {
    asm volatile("cp.async.cg.shared.global [%0], [%1], 16;" :: "r"(dst), "l"(src) : "memory");
}
#define CP_COMMIT()  asm volatile("cp.async.commit_group;" ::: "memory")
#define CP_WAIT0()   asm volatile("cp.async.wait_group 0;" ::: "memory")
#define CP_WAIT1()   asm volatile("cp.async.wait_group 1;" ::: "memory")

__device__ __forceinline__ void mma_f16(float c[4], const uint32_t a[4], const uint32_t b[2]) {
    asm("mma.sync.aligned.m16n8k16.row.col.f32.f16.f16.f32 "
        "{%0,%1,%2,%3}, {%4,%5,%6,%7}, {%8,%9}, {%0,%1,%2,%3};"
        : "+f"(c[0]), "+f"(c[1]), "+f"(c[2]), "+f"(c[3])
        : "r"(a[0]), "r"(a[1]), "r"(a[2]), "r"(a[3]), "r"(b[0]), "r"(b[1]));
}
__device__ __forceinline__ void ldsm_x4(uint32_t r[4], uint32_t a) {
    asm volatile("ldmatrix.sync.aligned.m8n8.x4.shared.b16 {%0,%1,%2,%3}, [%4];"
                 : "=r"(r[0]), "=r"(r[1]), "=r"(r[2]), "=r"(r[3]) : "r"(a));
}
__device__ __forceinline__ void ldsm_x2(uint32_t r[2], uint32_t a) {
    asm volatile("ldmatrix.sync.aligned.m8n8.x2.shared.b16 {%0,%1}, [%2];"
                 : "=r"(r[0]), "=r"(r[1]) : "r"(a));
}
__device__ __forceinline__ void ldsm_x2t(uint32_t r[2], uint32_t a) {
    asm volatile("ldmatrix.sync.aligned.m8n8.x2.trans.shared.b16 {%0,%1}, [%2];"
                 : "=r"(r[0]), "=r"(r[1]) : "r"(a));
}
__device__ __forceinline__ uint32_t packh(float a, float b) {
    __half2 h = __floats2half2_rn(a, b);
    return *reinterpret_cast<uint32_t*>(&h);
}
__device__ __forceinline__ void split2h(float a, float b, uint32_t& hp, uint32_t& lp) {
    __half2 h = __floats2half2_rn(a, b);
    hp = *reinterpret_cast<uint32_t*>(&h);
    const float ra = a - __half2float(__low2half(h));
    const float rb = b - __half2float(__high2half(h));
    __half2 l = __floats2half2_rn(ra, rb);
    lp = *reinterpret_cast<uint32_t*>(&l);
}
__device__ __forceinline__ float ex2f(float x) {
    float r; asm("ex2.approx.f32 %0, %1;" : "=f"(r) : "f"(x)); return r;
}

// ---------------- fused fp32 -> fp16 conversions (one launch) ----------------
#define N_X4   1048576
#define N_WQ4  786432
#define N_WO4  262144
#define SPLIT_TOTAL (2 * N_X4 + 2 * N_WQ4 + 2 * N_WO4)

__global__ void split_all(const float* __restrict__ x_r, const float* __restrict__ x_i,
                          const float* __restrict__ wq_r, const float* __restrict__ wq_i,
                          const float* __restrict__ wo_r, const float* __restrict__ wo_i)
{
    for (int i = blockIdx.x * blockDim.x + threadIdx.x; i < SPLIT_TOTAL;
         i += gridDim.x * blockDim.x) {
        if (i < 2 * N_X4) {                 // x: plain fp16
            const float* src = (i < N_X4) ? x_r : x_i;
            __half* hi = (i < N_X4) ? g_xrh : g_xih;
            const int off = (i < N_X4) ? i : i - N_X4;
            float4 v = ((const float4*)src)[off];
            uint2 hp;
            hp.x = packh(v.x, v.y); hp.y = packh(v.z, v.w);
            ((uint2*)hi)[off] = hp;
        } else {                            // weights: hi/lo
            const float* src; __half *hi, *lo; int off;
            if (i < 2 * N_X4 + 2 * N_WQ4) {
                const int k = i - 2 * N_X4;
                if (k < N_WQ4) { src = wq_r; hi = g_wqrh; lo = g_wqrl; off = k; }
                else           { src = wq_i; hi = g_wqih; lo = g_wqil; off = k - N_WQ4; }
            } else {
                const int k = i - 2 * N_X4 - 2 * N_WQ4;
                if (k < N_WO4) { src = wo_r; hi = g_worh; lo = g_worl; off = k; }
                else           { src = wo_i; hi = g_woih; lo = g_woil; off = k - N_WO4; }
            }
            float4 v = ((const float4*)src)[off];
            uint2 hp, lp;
            split2h(v.x, v.y, hp.x, lp.x);
            split2h(v.z, v.w, hp.y, lp.y);
            ((uint2*)hi)[off] = hp;
            ((uint2*)lo)[off] = lp;
        }
    }
}

// ============================================================
// HMMA fp16 2-term GEMM: D = A @ (Bh+Bl)^T + bias.
// 3-stage cp.async pipeline. V written plain in QKV epilogue.
// ============================================================
#define T128_B 10240
#define STG_B  (3 * T128_B)
#define GEMM_SMEM (3 * STG_B)
#define NCHUNK 32

template<int QKV>
__global__ __launch_bounds__(256, 2)
void gemm_f16(const float* __restrict__ bias_r, const float* __restrict__ bias_i,
              float* __restrict__ Yr, float* __restrict__ Yi)
{
    extern __shared__ char smc[];
    const uint32_t sb = smem_u32(smc);
    const int tid = threadIdx.x;
    const int wid = tid >> 5, lid = tid & 31;
    const int wm = wid >> 2, wn = wid & 3;
    const int g = lid >> 2, tig = lid & 3;
    const int n0 = blockIdx.x * 128;
    const int m0 = blockIdx.y * 128;
    const int z  = blockIdx.z;

    const __half *A, *Bh, *Bl;
    const float* bias;
    if (QKV) {
        if (z == 0) { A = g_xrh;  Bh = g_wqrh; Bl = g_wqrl; bias = bias_r; }
        else        { A = g_xih;  Bh = g_wqih; Bl = g_wqil; bias = bias_i; }
    } else {
        if (z == 0) { A = g_oarh; Bh = g_worh; Bl = g_worl; bias = bias_r; }
        else        { A = g_oaih; Bh = g_woih; Bl = g_woil; bias = bias_i; }
    }
    float* Y = (z == 0) ? Yr : Yi;

    auto issue_cp = [&](int chunk, int s) {
        const int k0 = chunk * 32;
        const uint32_t base = sb + (uint32_t)s * STG_B;
#pragma unroll
        for (int i = 0; i < 6; ++i) {
            const int lin = tid + i * 256;
            if (lin < 512) {
                const int row = lin >> 2, c = lin & 3;
                cp_async16(base + row * 80 + c * 16,
                           A + (size_t)(m0 + row) * DIM + k0 + c * 8);
            } else {
                const int l2 = lin - 512;
                const int hl = l2 >> 9, rc = l2 & 511;
                const int row = rc >> 2, c = rc & 3;
                cp_async16(base + T128_B + hl * T128_B + row * 80 + c * 16,
                           (hl ? Bl : Bh) + (size_t)(n0 + row) * DIM + k0 + c * 8);
            }
        }
    };

    const uint32_t a_rel = (uint32_t)((wm * 64 + (lid & 15)) * 80 + ((lid >> 4) << 4));
    const uint32_t b_rel = (uint32_t)((wn * 32 + (lid & 7) + ((lid & 16) >> 1)) * 80 +
                                      ((lid & 8) << 1));

    float acc[4][4][4];
#pragma unroll
    for (int a = 0; a < 4; a++)
#pragma unroll
        for (int b = 0; b < 4; b++)
#pragma unroll
            for (int c = 0; c < 4; c++) acc[a][b][c] = 0.f;

    issue_cp(0, 0); CP_COMMIT();
    issue_cp(1, 1); CP_COMMIT();

    int stage = 0;
    for (int j = 0; j < NCHUNK; ++j) {
        if (j + 1 < NCHUNK) { CP_WAIT1(); } else { CP_WAIT0(); }
        __syncthreads();
        if (j + 2 < NCHUNK) {
            issue_cp(j + 2, (stage + 2 >= 3) ? stage - 1 : stage + 2);
            CP_COMMIT();
        }

        const uint32_t st  = sb + (uint32_t)stage * STG_B;
        const uint32_t aA  = st + a_rel;
        const uint32_t aBh = st + T128_B + b_rel;
        const uint32_t aBl = aBh + T128_B;

#pragma unroll
        for (int ks = 0; ks < 2; ++ks) {
            uint32_t bh01[4], bh23[4], bl01[4], bl23[4];
            ldsm_x4(bh01, aBh + ks * 32);
            ldsm_x4(bh23, aBh + 1280 + ks * 32);
            ldsm_x4(bl01, aBl + ks * 32);
            ldsm_x4(bl23, aBl + 1280 + ks * 32);
#pragma unroll
            for (int mi = 0; mi < 4; ++mi) {
                uint32_t ah[4];
                ldsm_x4(ah, aA + mi * 1280 + ks * 32);
                mma_f16(acc[mi][0], ah, bh01);
                mma_f16(acc[mi][1], ah, bh01 + 2);
                mma_f16(acc[mi][2], ah, bh23);
                mma_f16(acc[mi][3], ah, bh23 + 2);
                mma_f16(acc[mi][0], ah, bl01);
                mma_f16(acc[mi][1], ah, bl01 + 2);
                mma_f16(acc[mi][2], ah, bl23);
                mma_f16(acc[mi][3], ah, bl23 + 2);
            }
        }
        stage = (stage + 1 == 3) ? 0 : stage + 1;
    }

    // ---- epilogue ----
#pragma unroll
    for (int nb = 0; nb < 4; ++nb) {
        const int n = n0 + wn * 32 + nb * 8 + tig * 2;
        const float b0v = bias[n], b1v = bias[n + 1];
#pragma unroll
        for (int mi = 0; mi < 4; ++mi) {
            const int mlo = m0 + wm * 64 + mi * 16 + g;
#pragma unroll
            for (int half = 0; half < 2; ++half) {
                const int m = mlo + half * 8;
                const float y0 = acc[mi][nb][half * 2 + 0] + b0v;
                const float y1 = acc[mi][nb][half * 2 + 1] + b1v;
                if (!QKV) {
                    *(float2*)&Y[(size_t)m * DIM + n] = make_float2(y0, y1);
                } else {
                    const int which = n >> 10;
                    const int h = (n >> 6) & 15;
                    const int d = n & 63;
                    const int bh = (m >> 11) * HEADS + h;
                    const int ns = m & 2047;
                    const uint32_t hp = packh(y0, y1);
                    if (which == 2) {                  // V: plain
                        const size_t idx = ((size_t)bh * SEQ + ns) * HD + d;
                        if (z == 0) *(uint32_t*)&g_vrh[idx] = hp;
                        else        *(uint32_t*)&g_vih[idx] = hp;
                    } else {                           // Q and K: plain
                        const size_t idx = ((size_t)bh * SEQ + ns) * 128 + d + (z ? 64 : 0);
                        if (which == 0) *(uint32_t*)&g_qph[idx] = hp;
                        else            *(uint32_t*)&g_kph[idx] = hp;
                    }
                }
            }
        }
    }
}

// ============================================================
// HMMA flash complex attention: Q, K, P, V all plain fp16.
// No-max softmax (p biased by 2^-PBIAS). 2 CTAs/SM.
// ============================================================
#define NT 32
#define QSM   0u
#define KSM   17408u
#define VSM(b) (34816u + (uint32_t)(b) * 9216u)
#define ATT_SMEM 53248

__global__ __launch_bounds__(128, 2)
void attn_mma()
{
    extern __shared__ char smb[];
    const uint32_t sb = smem_u32(smb);
    const int tid = threadIdx.x, w = tid >> 5, L = tid & 31;
    const int bh = blockIdx.y, qt = blockIdx.x;
    const size_t kvrow0 = (size_t)bh * SEQ;

    auto issueQ = [&]() {
        const size_t qb = (kvrow0 + (size_t)qt * 64) * 128;
#pragma unroll
        for (int i = 0; i < 8; ++i) {
            const int lin = tid + i * 128;
            const int row = lin >> 4, ch = lin & 15;
            cp_async16(sb + QSM + row * 272 + ch * 16, g_qph + qb + row * 128 + ch * 8);
        }
    };
    auto issueK = [&](int kt) {
#pragma unroll
        for (int i = 0; i < 8; ++i) {
            const int lin = tid + i * 128;
            const int row = lin >> 4, ch = lin & 15;
            cp_async16(sb + KSM + row * 272 + ch * 16,
                       g_kph + (kvrow0 + kt * 64 + row) * 128 + ch * 8);
        }
    };
    auto issueV = [&](int kt) {
#pragma unroll
        for (int i = 0; i < 8; ++i) {
            const int lin = tid + i * 128;
            const int bf = lin >> 9, rem = lin & 511, row = rem >> 3, ch = rem & 7;
            cp_async16(sb + VSM(bf) + row * 144 + ch * 16,
                       (bf ? g_vih : g_vrh) + (kvrow0 + kt * 64 + row) * HD + ch * 8);
        }
    };

    float Or[8][4], Oi[8][4];
#pragma unroll
    for (int nb = 0; nb < 8; ++nb)
#pragma unroll
        for (int e = 0; e < 4; ++e) { Or[nb][e] = 0.f; Oi[nb][e] = 0.f; }
    float l0 = 0.f, l1 = 0.f;

    const uint32_t a_off = (uint32_t)((w * 16 + (L & 7) + (L & 8)) * 272 + ((L & 16) ? 16 : 0));
    const uint32_t brow  = (uint32_t)((L & 7) * 272 + ((L & 8) ? 16 : 0));
    const uint32_t vrow  = (uint32_t)(((L & 7) + (L & 8)) * 144);

    issueQ(); issueK(0); CP_COMMIT();
    issueV(0); CP_COMMIT();

    for (int j = 0; j < NT; ++j) {
        CP_WAIT1();
        __syncthreads();

        float Sr[8][4], Si[8][4];
#pragma unroll
        for (int nb = 0; nb < 8; ++nb)
#pragma unroll
            for (int e = 0; e < 4; ++e) { Sr[nb][e] = 0.f; Si[nb][e] = 0.f; }

        // ---- scores: Sr = [Qr|Qi]·K^T, Si = [Qi|-Qr]·K^T ----
#pragma unroll
        for (int c = 0; c < 4; ++c) {
            uint32_t fh[4], gh[4], nh[4];
            ldsm_x4(fh, sb + QSM + a_off + c * 32);
            ldsm_x4(gh, sb + QSM + a_off + (c + 4) * 32);
#pragma unroll
            for (int r = 0; r < 4; ++r) nh[r] = fh[r] ^ 0x80008000u;
#pragma unroll
            for (int nb = 0; nb < 8; ++nb) {
                const uint32_t ba = (uint32_t)nb * 2176u + brow;
                uint32_t bc[2], bd[2];
                ldsm_x2(bc, sb + KSM + ba + c * 32);
                ldsm_x2(bd, sb + KSM + ba + (c + 4) * 32);
                mma_f16(Sr[nb], fh, bc); mma_f16(Si[nb], gh, bc);
                mma_f16(Sr[nb], gh, bd); mma_f16(Si[nb], nh, bd);
            }
        }
        __syncthreads();

        if (j + 1 < NT) { issueK(j + 1); CP_COMMIT(); }

        // ---- no-max softmax: p' = 2^(C*mag - PBIAS) ----
#pragma unroll
        for (int nb = 0; nb < 8; ++nb)
#pragma unroll
            for (int e = 0; e < 4; ++e) {
                const float x = fmaf(Sr[nb][e], Sr[nb][e], Si[nb][e] * Si[nb][e]);
                float rs; asm("rsqrt.approx.f32 %0, %1;" : "=f"(rs) : "f"(x + 1e-30f));
                const float p = ex2f((EXP_C * x) * rs - PBIAS);
                Sr[nb][e] = p;
                if (e < 2) l0 += p; else l1 += p;
            }

        // ---- pack P (plain fp16) ----
        uint32_t Pf[4][4];
#pragma unroll
        for (int kc = 0; kc < 4; ++kc) {
            Pf[kc][0] = packh(Sr[2 * kc][0],     Sr[2 * kc][1]);
            Pf[kc][1] = packh(Sr[2 * kc][2],     Sr[2 * kc][3]);
            Pf[kc][2] = packh(Sr[2 * kc + 1][0], Sr[2 * kc + 1][1]);
            Pf[kc][3] = packh(Sr[2 * kc + 1][2], Sr[2 * kc + 1][3]);
        }

        if (j + 1 < NT) { CP_WAIT1(); } else { CP_WAIT0(); }
        __syncthreads();

        // ---- PV: O += P @ V (plain) ----
#pragma unroll
        for (int kc = 0; kc < 4; ++kc) {
            const uint32_t va = vrow + (uint32_t)kc * 2304u;
#pragma unroll
            for (int nb = 0; nb < 8; ++nb) {
                uint32_t vr_[2], vi_[2];
                ldsm_x2t(vr_, sb + VSM(0) + va + nb * 16);
                ldsm_x2t(vi_, sb + VSM(1) + va + nb * 16);
                mma_f16(Or[nb], Pf[kc], vr_);
                mma_f16(Oi[nb], Pf[kc], vi_);
            }
        }
        __syncthreads();

        if (j + 1 < NT) { issueV(j + 1); CP_COMMIT(); }
    }

    // ---- epilogue ----
    l0 += __shfl_xor_sync(0xffffffffu, l0, 1);
    l0 += __shfl_xor_sync(0xffffffffu, l0, 2);
    l1 += __shfl_xor_sync(0xffffffffu, l1, 1);
    l1 += __shfl_xor_sync(0xffffffffu, l1, 2);
    const float inv0 = 1.f / l0, inv1 = 1.f / l1;
    const int b  = bh >> 4;
    const int hh = bh & 15;
    const int r0 = qt * 64 + w * 16 + (L >> 2);
    const size_t base0 = ((size_t)b * SEQ + r0) * DIM + hh * 64;
    const size_t base1 = base0 + (size_t)8 * DIM;
#pragma unroll
    for (int nb = 0; nb < 8; ++nb) {
        const int col = nb * 8 + 2 * (L & 3);
        *(uint32_t*)&g_oarh[base0 + col] = packh(Or[nb][0] * inv0, Or[nb][1] * inv0);
        *(uint32_t*)&g_oaih[base0 + col] = packh(Oi[nb][0] * inv0, Oi[nb][1] * inv0);
        *(uint32_t*)&g_oarh[base1 + col] = packh(Or[nb][2] * inv1, Or[nb][3] * inv1);
        *(uint32_t*)&g_oaih[base1 + col] = packh(Oi[nb][2] * inv1, Oi[nb][3] * inv1);
    }
}

// ============================================================
extern "C" void kernel_launch(void* const* d_in, const int* in_sizes, int n_in,
                              void* d_out, int out_size)
{
    const float* x_r    = (const float*)d_in[0];
    const float* x_i    = (const float*)d_in[1];
    const float* Wqkv_r = (const float*)d_in[2];
    const float* bqkv_r = (const float*)d_in[3];
    const float* Wqkv_i = (const float*)d_in[4];
    const float* bqkv_i = (const float*)d_in[5];
    const float* Wout_r = (const float*)d_in[6];
    const float* bout_r = (const float*)d_in[7];
    const float* Wout_i = (const float*)d_in[8];
    const float* bout_i = (const float*)d_in[9];

    cudaFuncSetAttribute(gemm_f16<1>, cudaFuncAttributeMaxDynamicSharedMemorySize, GEMM_SMEM);
    cudaFuncSetAttribute(gemm_f16<0>, cudaFuncAttributeMaxDynamicSharedMemorySize, GEMM_SMEM);
    cudaFuncSetAttribute(attn_mma,    cudaFuncAttributeMaxDynamicSharedMemorySize, ATT_SMEM);

    // 1) fused conversions
    split_all<<<2048, 256>>>(x_r, x_i, Wqkv_r, Wqkv_i, Wout_r, Wout_i);

    // 2) QKV projections (real + imag in one launch)
    dim3 gq(QKV_N / 128, M_TOTAL / 128, 2);    // (24, 32, 2)
    gemm_f16<1><<<gq, 256, GEMM_SMEM>>>(bqkv_r, bqkv_i, nullptr, nullptr);

    // 3) HMMA flash complex attention
    dim3 ga(SEQ / 64, BH);                     // (32, 32)
    attn_mma<<<ga, 128, ATT_SMEM>>>();

    // 4) output projections (real + imag in one launch)
    float* outr = (float*)d_out;
    float* outi = outr + (size_t)OUT_ELEMS;
    dim3 go(DIM / 128, M_TOTAL / 128, 2);      // (8, 32, 2)
    gemm_f16<0><<<go, 256, GEMM_SMEM>>>(bout_r, bout_i, outr, outi);
}

// round 14
// speedup vs baseline: 2.5269x; 1.2899x over previous
#include <cuda_runtime.h>
#include <cuda_fp16.h>
#include <cstdint>
#include <math.h>

#define B_SZ   2
#define SEQ    2048
#define DIM    1024
#define HEADS  16
#define HD     64
#define SCALE  0.125f
#define EXP_C  0.1803368801111243f   /* SCALE * log2(e) */
#define PBIAS  4.0f
#define M_TOTAL (B_SZ * SEQ)
#define QKV_N   (3 * DIM)
#define OUT_ELEMS  (B_SZ * SEQ * DIM)
#define BH      (B_SZ * HEADS)
#define PACKED_ELEMS (BH * SEQ * 128)
#define V_ELEMS      (BH * SEQ * HD)

// ---------------- scratch (static device globals, fp16, all plain) ----------------
__device__ __half g_xrh[OUT_ELEMS], g_xih[OUT_ELEMS];                  // x
__device__ __half g_wqr[QKV_N * DIM], g_wqi[QKV_N * DIM];              // Wqkv
__device__ __half g_wor[DIM * DIM], g_woi[DIM * DIM];                  // Wout
__device__ __half g_qph[PACKED_ELEMS];                                 // Q packed
__device__ __half g_kph[PACKED_ELEMS];                                 // K packed
__device__ __half g_vrh[V_ELEMS], g_vih[V_ELEMS];                      // V
__device__ __half g_oarh[OUT_ELEMS], g_oaih[OUT_ELEMS];                // O

// ---------------- helpers ----------------
__device__ __forceinline__ uint32_t smem_u32(const void* p) {
    uint32_t a;
    asm("{ .reg .u64 t; cvta.to.shared.u64 t, %1; cvt.u32.u64 %0, t; }" : "=r"(a) : "l"(p));
    return a;
}
__device__ __forceinline__ void cp_async16(uint32_t dst, const void* src) {
    asm volatile("cp.async.cg.shared.global [%0], [%1], 16;" :: "r"(dst), "l"(src) : "memory");
}
#define CP_COMMIT()  asm volatile("cp.async.commit_group;" ::: "memory")
#define CP_WAIT0()   asm volatile("cp.async.wait_group 0;" ::: "memory")
#define CP_WAIT1()   asm volatile("cp.async.wait_group 1;" ::: "memory")

__device__ __forceinline__ void mma_f16(float c[4], const uint32_t a[4], const uint32_t b[2]) {
    asm("mma.sync.aligned.m16n8k16.row.col.f32.f16.f16.f32 "
        "{%0,%1,%2,%3}, {%4,%5,%6,%7}, {%8,%9}, {%0,%1,%2,%3};"
        : "+f"(c[0]), "+f"(c[1]), "+f"(c[2]), "+f"(c[3])
        : "r"(a[0]), "r"(a[1]), "r"(a[2]), "r"(a[3]), "r"(b[0]), "r"(b[1]));
}
__device__ __forceinline__ void ldsm_x4(uint32_t r[4], uint32_t a) {
    asm volatile("ldmatrix.sync.aligned.m8n8.x4.shared.b16 {%0,%1,%2,%3}, [%4];"
                 : "=r"(r[0]), "=r"(r[1]), "=r"(r[2]), "=r"(r[3]) : "r"(a));
}
__device__ __forceinline__ void ldsm_x2(uint32_t r[2], uint32_t a) {
    asm volatile("ldmatrix.sync.aligned.m8n8.x2.shared.b16 {%0,%1}, [%2];"
                 : "=r"(r[0]), "=r"(r[1]) : "r"(a));
}
__device__ __forceinline__ void ldsm_x2t(uint32_t r[2], uint32_t a) {
    asm volatile("ldmatrix.sync.aligned.m8n8.x2.trans.shared.b16 {%0,%1}, [%2];"
                 : "=r"(r[0]), "=r"(r[1]) : "r"(a));
}
__device__ __forceinline__ uint32_t packh(float a, float b) {
    __half2 h = __floats2half2_rn(a, b);
    return *reinterpret_cast<uint32_t*>(&h);
}
__device__ __forceinline__ float ex2f(float x) {
    float r; asm("ex2.approx.f32 %0, %1;" : "=f"(r) : "f"(x)); return r;
}

// ---------------- fused fp32 -> fp16 conversions (one launch, all plain) ----------------
#define N_X4   1048576      /* OUT_ELEMS/4  */
#define N_WQ4  786432       /* QKV_N*DIM/4  */
#define N_WO4  262144       /* DIM*DIM/4    */
#define SPLIT_TOTAL (2 * N_X4 + 2 * N_WQ4 + 2 * N_WO4)

__global__ void split_all(const float* __restrict__ x_r, const float* __restrict__ x_i,
                          const float* __restrict__ wq_r, const float* __restrict__ wq_i,
                          const float* __restrict__ wo_r, const float* __restrict__ wo_i)
{
    for (int i = blockIdx.x * blockDim.x + threadIdx.x; i < SPLIT_TOTAL;
         i += gridDim.x * blockDim.x) {
        const float* src; __half* dst; int off;
        if (i < 2 * N_X4) {
            if (i < N_X4) { src = x_r; dst = g_xrh; off = i; }
            else          { src = x_i; dst = g_xih; off = i - N_X4; }
        } else if (i < 2 * N_X4 + 2 * N_WQ4) {
            const int k = i - 2 * N_X4;
            if (k < N_WQ4) { src = wq_r; dst = g_wqr; off = k; }
            else           { src = wq_i; dst = g_wqi; off = k - N_WQ4; }
        } else {
            const int k = i - 2 * N_X4 - 2 * N_WQ4;
            if (k < N_WO4) { src = wo_r; dst = g_wor; off = k; }
            else           { src = wo_i; dst = g_woi; off = k - N_WO4; }
        }
        float4 v = ((const float4*)src)[off];
        uint2 hp;
        hp.x = packh(v.x, v.y); hp.y = packh(v.z, v.w);
        ((uint2*)dst)[off] = hp;
    }
}

// ============================================================
// HMMA plain-fp16 GEMM: D = A @ B^T + bias.
// 3-stage cp.async pipeline, CTA 128x128, K-chunk 32,
// 8 warps (2x4), warp tile 64x32, 2 CTA/SM.
// ============================================================
#define T128_B 10240                   /* 128 rows x 80 B */
#define STG_B  (2 * T128_B)            /* A, B            */
#define GEMM_SMEM (3 * STG_B)          /* 61440           */
#define NCHUNK 32

template<int QKV>
__global__ __launch_bounds__(256, 2)
void gemm_f16(const float* __restrict__ bias_r, const float* __restrict__ bias_i,
              float* __restrict__ Yr, float* __restrict__ Yi)
{
    extern __shared__ char smc[];
    const uint32_t sb = smem_u32(smc);
    const int tid = threadIdx.x;
    const int wid = tid >> 5, lid = tid & 31;
    const int wm = wid >> 2, wn = wid & 3;
    const int g = lid >> 2, tig = lid & 3;
    const int n0 = blockIdx.x * 128;
    const int m0 = blockIdx.y * 128;
    const int z  = blockIdx.z;

    const __half *A, *B;
    const float* bias;
    if (QKV) {
        if (z == 0) { A = g_xrh;  B = g_wqr; bias = bias_r; }
        else        { A = g_xih;  B = g_wqi; bias = bias_i; }
    } else {
        if (z == 0) { A = g_oarh; B = g_wor; bias = bias_r; }
        else        { A = g_oaih; B = g_woi; bias = bias_i; }
    }
    float* Y = (z == 0) ? Yr : Yi;

    auto issue_cp = [&](int chunk, int s) {
        const int k0 = chunk * 32;
        const uint32_t base = sb + (uint32_t)s * STG_B;
#pragma unroll
        for (int i = 0; i < 4; ++i) {
            const int lin = tid + i * 256;           // 0..1023
            if (lin < 512) {                          // A
                const int row = lin >> 2, c = lin & 3;
                cp_async16(base + row * 80 + c * 16,
                           A + (size_t)(m0 + row) * DIM + k0 + c * 8);
            } else {                                  // B
                const int l2 = lin - 512;
                const int row = l2 >> 2, c = l2 & 3;
                cp_async16(base + T128_B + row * 80 + c * 16,
                           B + (size_t)(n0 + row) * DIM + k0 + c * 8);
            }
        }
    };

    const uint32_t a_rel = (uint32_t)((wm * 64 + (lid & 15)) * 80 + ((lid >> 4) << 4));
    const uint32_t b_rel = (uint32_t)((wn * 32 + (lid & 7) + ((lid & 16) >> 1)) * 80 +
                                      ((lid & 8) << 1));

    float acc[4][4][4];
#pragma unroll
    for (int a = 0; a < 4; a++)
#pragma unroll
        for (int b = 0; b < 4; b++)
#pragma unroll
            for (int c = 0; c < 4; c++) acc[a][b][c] = 0.f;

    issue_cp(0, 0); CP_COMMIT();
    issue_cp(1, 1); CP_COMMIT();

    int stage = 0;
    for (int j = 0; j < NCHUNK; ++j) {
        if (j + 1 < NCHUNK) { CP_WAIT1(); } else { CP_WAIT0(); }
        __syncthreads();
        if (j + 2 < NCHUNK) {
            issue_cp(j + 2, (stage + 2 >= 3) ? stage - 1 : stage + 2);
            CP_COMMIT();
        }

        const uint32_t st = sb + (uint32_t)stage * STG_B;
        const uint32_t aA = st + a_rel;
        const uint32_t aB = st + T128_B + b_rel;

#pragma unroll
        for (int ks = 0; ks < 2; ++ks) {
            uint32_t b01[4], b23[4];
            ldsm_x4(b01, aB + ks * 32);
            ldsm_x4(b23, aB + 1280 + ks * 32);
#pragma unroll
            for (int mi = 0; mi < 4; ++mi) {
                uint32_t ah[4];
                ldsm_x4(ah, aA + mi * 1280 + ks * 32);
                mma_f16(acc[mi][0], ah, b01);
                mma_f16(acc[mi][1], ah, b01 + 2);
                mma_f16(acc[mi][2], ah, b23);
                mma_f16(acc[mi][3], ah, b23 + 2);
            }
        }
        stage = (stage + 1 == 3) ? 0 : stage + 1;
    }

    // ---- epilogue ----
#pragma unroll
    for (int nb = 0; nb < 4; ++nb) {
        const int n = n0 + wn * 32 + nb * 8 + tig * 2;
        const float b0v = bias[n], b1v = bias[n + 1];
#pragma unroll
        for (int mi = 0; mi < 4; ++mi) {
            const int mlo = m0 + wm * 64 + mi * 16 + g;
#pragma unroll
            for (int half = 0; half < 2; ++half) {
                const int m = mlo + half * 8;
                const float y0 = acc[mi][nb][half * 2 + 0] + b0v;
                const float y1 = acc[mi][nb][half * 2 + 1] + b1v;
                if (!QKV) {
                    *(float2*)&Y[(size_t)m * DIM + n] = make_float2(y0, y1);
                } else {
                    const int which = n >> 10;
                    const int h = (n >> 6) & 15;
                    const int d = n & 63;
                    const int bh = (m >> 11) * HEADS + h;
                    const int ns = m & 2047;
                    const uint32_t hp = packh(y0, y1);
                    if (which == 2) {                  // V
                        const size_t idx = ((size_t)bh * SEQ + ns) * HD + d;
                        if (z == 0) *(uint32_t*)&g_vrh[idx] = hp;
                        else        *(uint32_t*)&g_vih[idx] = hp;
                    } else {                           // Q / K
                        const size_t idx = ((size_t)bh * SEQ + ns) * 128 + d + (z ? 64 : 0);
                        if (which == 0) *(uint32_t*)&g_qph[idx] = hp;
                        else            *(uint32_t*)&g_kph[idx] = hp;
                    }
                }
            }
        }
    }
}

// ============================================================
// HMMA flash complex attention (unchanged from Round 13).
// ============================================================
#define NT 32
#define QSM   0u
#define KSM   17408u
#define VSM(b) (34816u + (uint32_t)(b) * 9216u)
#define ATT_SMEM 53248

__global__ __launch_bounds__(128, 2)
void attn_mma()
{
    extern __shared__ char smb[];
    const uint32_t sb = smem_u32(smb);
    const int tid = threadIdx.x, w = tid >> 5, L = tid & 31;
    const int bh = blockIdx.y, qt = blockIdx.x;
    const size_t kvrow0 = (size_t)bh * SEQ;

    auto issueQ = [&]() {
        const size_t qb = (kvrow0 + (size_t)qt * 64) * 128;
#pragma unroll
        for (int i = 0; i < 8; ++i) {
            const int lin = tid + i * 128;
            const int row = lin >> 4, ch = lin & 15;
            cp_async16(sb + QSM + row * 272 + ch * 16, g_qph + qb + row * 128 + ch * 8);
        }
    };
    auto issueK = [&](int kt) {
#pragma unroll
        for (int i = 0; i < 8; ++i) {
            const int lin = tid + i * 128;
            const int row = lin >> 4, ch = lin & 15;
            cp_async16(sb + KSM + row * 272 + ch * 16,
                       g_kph + (kvrow0 + kt * 64 + row) * 128 + ch * 8);
        }
    };
    auto issueV = [&](int kt) {
#pragma unroll
        for (int i = 0; i < 8; ++i) {
            const int lin = tid + i * 128;
            const int bf = lin >> 9, rem = lin & 511, row = rem >> 3, ch = rem & 7;
            cp_async16(sb + VSM(bf) + row * 144 + ch * 16,
                       (bf ? g_vih : g_vrh) + (kvrow0 + kt * 64 + row) * HD + ch * 8);
        }
    };

    float Or[8][4], Oi[8][4];
#pragma unroll
    for (int nb = 0; nb < 8; ++nb)
#pragma unroll
        for (int e = 0; e < 4; ++e) { Or[nb][e] = 0.f; Oi[nb][e] = 0.f; }
    float l0 = 0.f, l1 = 0.f;

    const uint32_t a_off = (uint32_t)((w * 16 + (L & 7) + (L & 8)) * 272 + ((L & 16) ? 16 : 0));
    const uint32_t brow  = (uint32_t)((L & 7) * 272 + ((L & 8) ? 16 : 0));
    const uint32_t vrow  = (uint32_t)(((L & 7) + (L & 8)) * 144);

    issueQ(); issueK(0); CP_COMMIT();
    issueV(0); CP_COMMIT();

    for (int j = 0; j < NT; ++j) {
        CP_WAIT1();
        __syncthreads();

        float Sr[8][4], Si[8][4];
#pragma unroll
        for (int nb = 0; nb < 8; ++nb)
#pragma unroll
            for (int e = 0; e < 4; ++e) { Sr[nb][e] = 0.f; Si[nb][e] = 0.f; }

#pragma unroll
        for (int c = 0; c < 4; ++c) {
            uint32_t fh[4], gh[4], nh[4];
            ldsm_x4(fh, sb + QSM + a_off + c * 32);
            ldsm_x4(gh, sb + QSM + a_off + (c + 4) * 32);
#pragma unroll
            for (int r = 0; r < 4; ++r) nh[r] = fh[r] ^ 0x80008000u;
#pragma unroll
            for (int nb = 0; nb < 8; ++nb) {
                const uint32_t ba = (uint32_t)nb * 2176u + brow;
                uint32_t bc[2], bd[2];
                ldsm_x2(bc, sb + KSM + ba + c * 32);
                ldsm_x2(bd, sb + KSM + ba + (c + 4) * 32);
                mma_f16(Sr[nb], fh, bc); mma_f16(Si[nb], gh, bc);
                mma_f16(Sr[nb], gh, bd); mma_f16(Si[nb], nh, bd);
            }
        }
        __syncthreads();

        if (j + 1 < NT) { issueK(j + 1); CP_COMMIT(); }

#pragma unroll
        for (int nb = 0; nb < 8; ++nb)
#pragma unroll
            for (int e = 0; e < 4; ++e) {
                const float x = fmaf(Sr[nb][e], Sr[nb][e], Si[nb][e] * Si[nb][e]);
                float rs; asm("rsqrt.approx.f32 %0, %1;" : "=f"(rs) : "f"(x + 1e-30f));
                const float p = ex2f((EXP_C * x) * rs - PBIAS);
                Sr[nb][e] = p;
                if (e < 2) l0 += p; else l1 += p;
            }

        uint32_t Pf[4][4];
#pragma unroll
        for (int kc = 0; kc < 4; ++kc) {
            Pf[kc][0] = packh(Sr[2 * kc][0],     Sr[2 * kc][1]);
            Pf[kc][1] = packh(Sr[2 * kc][2],     Sr[2 * kc][3]);
            Pf[kc][2] = packh(Sr[2 * kc + 1][0], Sr[2 * kc + 1][1]);
            Pf[kc][3] = packh(Sr[2 * kc + 1][2], Sr[2 * kc + 1][3]);
        }

        if (j + 1 < NT) { CP_WAIT1(); } else { CP_WAIT0(); }
        __syncthreads();

#pragma unroll
        for (int kc = 0; kc < 4; ++kc) {
            const uint32_t va = vrow + (uint32_t)kc * 2304u;
#pragma unroll
            for (int nb = 0; nb < 8; ++nb) {
                uint32_t vr_[2], vi_[2];
                ldsm_x2t(vr_, sb + VSM(0) + va + nb * 16);
                ldsm_x2t(vi_, sb + VSM(1) + va + nb * 16);
                mma_f16(Or[nb], Pf[kc], vr_);
                mma_f16(Oi[nb], Pf[kc], vi_);
            }
        }
        __syncthreads();

        if (j + 1 < NT) { issueV(j + 1); CP_COMMIT(); }
    }

    l0 += __shfl_xor_sync(0xffffffffu, l0, 1);
    l0 += __shfl_xor_sync(0xffffffffu, l0, 2);
    l1 += __shfl_xor_sync(0xffffffffu, l1, 1);
    l1 += __shfl_xor_sync(0xffffffffu, l1, 2);
    const float inv0 = 1.f / l0, inv1 = 1.f / l1;
    const int b  = bh >> 4;
    const int hh = bh & 15;
    const int r0 = qt * 64 + w * 16 + (L >> 2);
    const size_t base0 = ((size_t)b * SEQ + r0) * DIM + hh * 64;
    const size_t base1 = base0 + (size_t)8 * DIM;
#pragma unroll
    for (int nb = 0; nb < 8; ++nb) {
        const int col = nb * 8 + 2 * (L & 3);
        *(uint32_t*)&g_oarh[base0 + col] = packh(Or[nb][0] * inv0, Or[nb][1] * inv0);
        *(uint32_t*)&g_oaih[base0 + col] = packh(Oi[nb][0] * inv0, Oi[nb][1] * inv0);
        *(uint32_t*)&g_oarh[base1 + col] = packh(Or[nb][2] * inv1, Or[nb][3] * inv1);
        *(uint32_t*)&g_oaih[base1 + col] = packh(Oi[nb][2] * inv1, Oi[nb][3] * inv1);
    }
}

// ============================================================
extern "C" void kernel_launch(void* const* d_in, const int* in_sizes, int n_in,
                              void* d_out, int out_size)
{
    const float* x_r    = (const float*)d_in[0];
    const float* x_i    = (const float*)d_in[1];
    const float* Wqkv_r = (const float*)d_in[2];
    const float* bqkv_r = (const float*)d_in[3];
    const float* Wqkv_i = (const float*)d_in[4];
    const float* bqkv_i = (const float*)d_in[5];
    const float* Wout_r = (const float*)d_in[6];
    const float* bout_r = (const float*)d_in[7];
    const float* Wout_i = (const float*)d_in[8];
    const float* bout_i = (const float*)d_in[9];

    cudaFuncSetAttribute(gemm_f16<1>, cudaFuncAttributeMaxDynamicSharedMemorySize, GEMM_SMEM);
    cudaFuncSetAttribute(gemm_f16<0>, cudaFuncAttributeMaxDynamicSharedMemorySize, GEMM_SMEM);
    cudaFuncSetAttribute(attn_mma,    cudaFuncAttributeMaxDynamicSharedMemorySize, ATT_SMEM);

    // 1) fused conversions
    split_all<<<2048, 256>>>(x_r, x_i, Wqkv_r, Wqkv_i, Wout_r, Wout_i);

    // 2) QKV projections (real + imag in one launch)
    dim3 gq(QKV_N / 128, M_TOTAL / 128, 2);    // (24, 32, 2)
    gemm_f16<1><<<gq, 256, GEMM_SMEM>>>(bqkv_r, bqkv_i, nullptr, nullptr);

    // 3) HMMA flash complex attention
    dim3 ga(SEQ / 64, BH);                     // (32, 32)
    attn_mma<<<ga, 128, ATT_SMEM>>>();

    // 4) output projections (real + imag in one launch)
    float* outr = (float*)d_out;
    float* outi = outr + (size_t)OUT_ELEMS;
    dim3 go(DIM / 128, M_TOTAL / 128, 2);      // (8, 32, 2)
    gemm_f16<0><<<go, 256, GEMM_SMEM>>>(bout_r, bout_i, outr, outi);
}

// round 15
// speedup vs baseline: 2.6073x; 1.0318x over previous
#include <cuda_runtime.h>
#include <cuda_fp16.h>
#include <cstdint>
#include <math.h>

#define B_SZ   2
#define SEQ    2048
#define DIM    1024
#define HEADS  16
#define HD     64
#define SCALE  0.125f
#define EXP_C  0.1803368801111243f   /* SCALE * log2(e) */
#define PBIAS  4.0f
#define M_TOTAL (B_SZ * SEQ)
#define QKV_N   (3 * DIM)
#define OUT_ELEMS  (B_SZ * SEQ * DIM)
#define BH      (B_SZ * HEADS)
#define PACKED_ELEMS (BH * SEQ * 128)
#define V_ELEMS      (BH * SEQ * HD)

// ---------------- scratch (static device globals, fp16, all plain) ----------------
__device__ __half g_xrh[OUT_ELEMS], g_xih[OUT_ELEMS];                  // x
__device__ __half g_wqr[QKV_N * DIM], g_wqi[QKV_N * DIM];              // Wqkv
__device__ __half g_wor[DIM * DIM], g_woi[DIM * DIM];                  // Wout
__device__ __half g_qph[PACKED_ELEMS];                                 // Q packed
__device__ __half g_kph[PACKED_ELEMS];                                 // K packed
__device__ __half g_vrh[V_ELEMS], g_vih[V_ELEMS];                      // V
__device__ __half g_oarh[OUT_ELEMS], g_oaih[OUT_ELEMS];                // O

// ---------------- helpers ----------------
__device__ __forceinline__ uint32_t smem_u32(const void* p) {
    uint32_t a;
    asm("{ .reg .u64 t; cvta.to.shared.u64 t, %1; cvt.u32.u64 %0, t; }" : "=r"(a) : "l"(p));
    return a;
}
__device__ __forceinline__ void cp_async16(uint32_t dst, const void* src) {
    asm volatile("cp.async.cg.shared.global [%0], [%1], 16;" :: "r"(dst), "l"(src) : "memory");
}
#define CP_COMMIT()  asm volatile("cp.async.commit_group;" ::: "memory")
#define CP_WAIT0()   asm volatile("cp.async.wait_group 0;" ::: "memory")
#define CP_WAIT1()   asm volatile("cp.async.wait_group 1;" ::: "memory")

__device__ __forceinline__ void mma_f16(float c[4], const uint32_t a[4], const uint32_t b[2]) {
    asm("mma.sync.aligned.m16n8k16.row.col.f32.f16.f16.f32 "
        "{%0,%1,%2,%3}, {%4,%5,%6,%7}, {%8,%9}, {%0,%1,%2,%3};"
        : "+f"(c[0]), "+f"(c[1]), "+f"(c[2]), "+f"(c[3])
        : "r"(a[0]), "r"(a[1]), "r"(a[2]), "r"(a[3]), "r"(b[0]), "r"(b[1]));
}
__device__ __forceinline__ void ldsm_x4(uint32_t r[4], uint32_t a) {
    asm volatile("ldmatrix.sync.aligned.m8n8.x4.shared.b16 {%0,%1,%2,%3}, [%4];"
                 : "=r"(r[0]), "=r"(r[1]), "=r"(r[2]), "=r"(r[3]) : "r"(a));
}
__device__ __forceinline__ void ldsm_x4t(uint32_t r[4], uint32_t a) {
    asm volatile("ldmatrix.sync.aligned.m8n8.x4.trans.shared.b16 {%0,%1,%2,%3}, [%4];"
                 : "=r"(r[0]), "=r"(r[1]), "=r"(r[2]), "=r"(r[3]) : "r"(a));
}
__device__ __forceinline__ uint32_t packh(float a, float b) {
    __half2 h = __floats2half2_rn(a, b);
    return *reinterpret_cast<uint32_t*>(&h);
}
__device__ __forceinline__ float ex2f(float x) {
    float r; asm("ex2.approx.f32 %0, %1;" : "=f"(r) : "f"(x)); return r;
}

// ---------------- fused fp32 -> fp16 conversions ----------------
#define N_X4   1048576
#define N_WQ4  786432
#define N_WO4  262144
#define SPLIT_TOTAL (2 * N_X4 + 2 * N_WQ4 + 2 * N_WO4)

__global__ void split_all(const float* __restrict__ x_r, const float* __restrict__ x_i,
                          const float* __restrict__ wq_r, const float* __restrict__ wq_i,
                          const float* __restrict__ wo_r, const float* __restrict__ wo_i)
{
    for (int i = blockIdx.x * blockDim.x + threadIdx.x; i < SPLIT_TOTAL;
         i += gridDim.x * blockDim.x) {
        const float* src; __half* dst; int off;
        if (i < 2 * N_X4) {
            if (i < N_X4) { src = x_r; dst = g_xrh; off = i; }
            else          { src = x_i; dst = g_xih; off = i - N_X4; }
        } else if (i < 2 * N_X4 + 2 * N_WQ4) {
            const int k = i - 2 * N_X4;
            if (k < N_WQ4) { src = wq_r; dst = g_wqr; off = k; }
            else           { src = wq_i; dst = g_wqi; off = k - N_WQ4; }
        } else {
            const int k = i - 2 * N_X4 - 2 * N_WQ4;
            if (k < N_WO4) { src = wo_r; dst = g_wor; off = k; }
            else           { src = wo_i; dst = g_woi; off = k - N_WO4; }
        }
        float4 v = ((const float4*)src)[off];
        uint2 hp;
        hp.x = packh(v.x, v.y); hp.y = packh(v.z, v.w);
        ((uint2*)dst)[off] = hp;
    }
}

// ============================================================
// HMMA plain-fp16 GEMM: D = A @ B^T + bias.
// K-chunk 64, 2-stage cp.async, ONE barrier per chunk.
// CTA 128x128, 8 warps (2x4), pitch 144 B, 2 CTA/SM.
// ============================================================
#define TILE_G 18432                   /* 128 rows x 144 B */
#define STG_B  (2 * TILE_G)            /* A, B             */
#define GEMM_SMEM (2 * STG_B)          /* 73728            */
#define NCHUNK 16

template<int QKV>
__global__ __launch_bounds__(256, 2)
void gemm_f16(const float* __restrict__ bias_r, const float* __restrict__ bias_i,
              float* __restrict__ Yr, float* __restrict__ Yi)
{
    extern __shared__ char smc[];
    const uint32_t sb = smem_u32(smc);
    const int tid = threadIdx.x;
    const int wid = tid >> 5, lid = tid & 31;
    const int wm = wid >> 2, wn = wid & 3;
    const int g = lid >> 2, tig = lid & 3;
    const int n0 = blockIdx.x * 128;
    const int m0 = blockIdx.y * 128;
    const int z  = blockIdx.z;

    const __half *A, *B;
    const float* bias;
    if (QKV) {
        if (z == 0) { A = g_xrh;  B = g_wqr; bias = bias_r; }
        else        { A = g_xih;  B = g_wqi; bias = bias_i; }
    } else {
        if (z == 0) { A = g_oarh; B = g_wor; bias = bias_r; }
        else        { A = g_oaih; B = g_woi; bias = bias_i; }
    }
    float* Y = (z == 0) ? Yr : Yi;

    auto issue_cp = [&](int chunk, int s) {
        const int k0 = chunk * 64;
        const uint32_t base = sb + (uint32_t)s * STG_B;
#pragma unroll
        for (int i = 0; i < 8; ++i) {
            const int lin = tid + i * 256;           // 0..2047
            const int t   = lin >> 10;               // 0=A, 1=B
            const int rc  = lin & 1023;
            const int row = rc >> 3, c = rc & 7;
            cp_async16(base + t * TILE_G + row * 144 + c * 16,
                       (t ? B : A) + (size_t)((t ? n0 : m0) + row) * DIM + k0 + c * 8);
        }
    };

    const uint32_t a_rel = (uint32_t)((wm * 64 + (lid & 15)) * 144 + ((lid >> 4) << 4));
    const uint32_t b_rel = (uint32_t)((wn * 32 + (lid & 7) + ((lid & 16) >> 1)) * 144 +
                                      ((lid & 8) << 1));

    float acc[4][4][4];
#pragma unroll
    for (int a = 0; a < 4; a++)
#pragma unroll
        for (int b = 0; b < 4; b++)
#pragma unroll
            for (int c = 0; c < 4; c++) acc[a][b][c] = 0.f;

    issue_cp(0, 0); CP_COMMIT();

    for (int j = 0; j < NCHUNK; ++j) {
        CP_WAIT0();
        __syncthreads();                 // chunk j visible; stage (j+1)&1 free
        if (j + 1 < NCHUNK) { issue_cp(j + 1, (j + 1) & 1); CP_COMMIT(); }

        const uint32_t st = sb + (uint32_t)(j & 1) * STG_B;
        const uint32_t aA = st + a_rel;
        const uint32_t aB = st + TILE_G + b_rel;

#pragma unroll
        for (int ks = 0; ks < 4; ++ks) {
            uint32_t b01[4], b23[4];
            ldsm_x4(b01, aB + ks * 32);
            ldsm_x4(b23, aB + 16 * 144 + ks * 32);
#pragma unroll
            for (int mi = 0; mi < 4; ++mi) {
                uint32_t ah[4];
                ldsm_x4(ah, aA + mi * (16 * 144) + ks * 32);
                mma_f16(acc[mi][0], ah, b01);
                mma_f16(acc[mi][1], ah, b01 + 2);
                mma_f16(acc[mi][2], ah, b23);
                mma_f16(acc[mi][3], ah, b23 + 2);
            }
        }
    }

    // ---- epilogue ----
#pragma unroll
    for (int nb = 0; nb < 4; ++nb) {
        const int n = n0 + wn * 32 + nb * 8 + tig * 2;
        const float b0v = bias[n], b1v = bias[n + 1];
#pragma unroll
        for (int mi = 0; mi < 4; ++mi) {
            const int mlo = m0 + wm * 64 + mi * 16 + g;
#pragma unroll
            for (int half = 0; half < 2; ++half) {
                const int m = mlo + half * 8;
                const float y0 = acc[mi][nb][half * 2 + 0] + b0v;
                const float y1 = acc[mi][nb][half * 2 + 1] + b1v;
                if (!QKV) {
                    *(float2*)&Y[(size_t)m * DIM + n] = make_float2(y0, y1);
                } else {
                    const int which = n >> 10;
                    const int h = (n >> 6) & 15;
                    const int d = n & 63;
                    const int bh = (m >> 11) * HEADS + h;
                    const int ns = m & 2047;
                    const uint32_t hp = packh(y0, y1);
                    if (which == 2) {
                        const size_t idx = ((size_t)bh * SEQ + ns) * HD + d;
                        if (z == 0) *(uint32_t*)&g_vrh[idx] = hp;
                        else        *(uint32_t*)&g_vih[idx] = hp;
                    } else {
                        const size_t idx = ((size_t)bh * SEQ + ns) * 128 + d + (z ? 64 : 0);
                        if (which == 0) *(uint32_t*)&g_qph[idx] = hp;
                        else            *(uint32_t*)&g_kph[idx] = hp;
                    }
                }
            }
        }
    }
}

// ============================================================
// HMMA flash complex attention: x4-paired K/V fragment loads.
// Math identical to Round 14 (same MMA order per accumulator).
// ============================================================
#define NT 32
#define QSM   0u
#define KSM   17408u
#define VSM(b) (34816u + (uint32_t)(b) * 9216u)
#define ATT_SMEM 53248

__global__ __launch_bounds__(128, 2)
void attn_mma()
{
    extern __shared__ char smb[];
    const uint32_t sb = smem_u32(smb);
    const int tid = threadIdx.x, w = tid >> 5, L = tid & 31;
    const int bh = blockIdx.y, qt = blockIdx.x;
    const size_t kvrow0 = (size_t)bh * SEQ;

    auto issueQ = [&]() {
        const size_t qb = (kvrow0 + (size_t)qt * 64) * 128;
#pragma unroll
        for (int i = 0; i < 8; ++i) {
            const int lin = tid + i * 128;
            const int row = lin >> 4, ch = lin & 15;
            cp_async16(sb + QSM + row * 272 + ch * 16, g_qph + qb + row * 128 + ch * 8);
        }
    };
    auto issueK = [&](int kt) {
#pragma unroll
        for (int i = 0; i < 8; ++i) {
            const int lin = tid + i * 128;
            const int row = lin >> 4, ch = lin & 15;
            cp_async16(sb + KSM + row * 272 + ch * 16,
                       g_kph + (kvrow0 + kt * 64 + row) * 128 + ch * 8);
        }
    };
    auto issueV = [&](int kt) {
#pragma unroll
        for (int i = 0; i < 8; ++i) {
            const int lin = tid + i * 128;
            const int bf = lin >> 9, rem = lin & 511, row = rem >> 3, ch = rem & 7;
            cp_async16(sb + VSM(bf) + row * 144 + ch * 16,
                       (bf ? g_vih : g_vrh) + (kvrow0 + kt * 64 + row) * HD + ch * 8);
        }
    };

    float Or[8][4], Oi[8][4];
#pragma unroll
    for (int nb = 0; nb < 8; ++nb)
#pragma unroll
        for (int e = 0; e < 4; ++e) { Or[nb][e] = 0.f; Oi[nb][e] = 0.f; }
    float l0 = 0.f, l1 = 0.f;

    const uint32_t a_off = (uint32_t)((w * 16 + (L & 7) + (L & 8)) * 272 + ((L & 16) ? 16 : 0));
    // paired K-fragment base: lanes 16-31 fetch the next nb group
    const uint32_t brow4 = (uint32_t)((L & 7) * 272 + ((L & 8) ? 16 : 0) +
                                      ((L & 16) ? 2176 : 0));
    // paired V-fragment base: lanes 16-31 fetch next nb column group
    const uint32_t vrow4 = (uint32_t)(((L & 7) + (L & 8)) * 144 + ((L & 16) ? 16 : 0));

    issueQ(); issueK(0); CP_COMMIT();
    issueV(0); CP_COMMIT();

    for (int j = 0; j < NT; ++j) {
        CP_WAIT1();
        __syncthreads();

        float Sr[8][4], Si[8][4];
#pragma unroll
        for (int nb = 0; nb < 8; ++nb)
#pragma unroll
            for (int e = 0; e < 4; ++e) { Sr[nb][e] = 0.f; Si[nb][e] = 0.f; }

        // ---- scores: Sr = [Qr|Qi]·K^T, Si = [Qi|-Qr]·K^T ----
#pragma unroll
        for (int c = 0; c < 4; ++c) {
            uint32_t fh[4], gh[4], nh[4];
            ldsm_x4(fh, sb + QSM + a_off + c * 32);
            ldsm_x4(gh, sb + QSM + a_off + (c + 4) * 32);
#pragma unroll
            for (int r = 0; r < 4; ++r) nh[r] = fh[r] ^ 0x80008000u;
#pragma unroll
            for (int nb = 0; nb < 8; nb += 2) {
                const uint32_t ba = sb + KSM + (uint32_t)nb * 2176u + brow4;
                uint32_t bc[4], bd[4];
                ldsm_x4(bc, ba + c * 32);
                ldsm_x4(bd, ba + (c + 4) * 32);
                mma_f16(Sr[nb],     fh, bc);     mma_f16(Si[nb],     gh, bc);
                mma_f16(Sr[nb],     gh, bd);     mma_f16(Si[nb],     nh, bd);
                mma_f16(Sr[nb + 1], fh, bc + 2); mma_f16(Si[nb + 1], gh, bc + 2);
                mma_f16(Sr[nb + 1], gh, bd + 2); mma_f16(Si[nb + 1], nh, bd + 2);
            }
        }
        __syncthreads();

        if (j + 1 < NT) { issueK(j + 1); CP_COMMIT(); }

        // ---- no-max softmax: p' = 2^(C*mag - PBIAS) ----
#pragma unroll
        for (int nb = 0; nb < 8; ++nb)
#pragma unroll
            for (int e = 0; e < 4; ++e) {
                const float x = fmaf(Sr[nb][e], Sr[nb][e], Si[nb][e] * Si[nb][e]);
                float rs; asm("rsqrt.approx.f32 %0, %1;" : "=f"(rs) : "f"(x + 1e-30f));
                const float p = ex2f((EXP_C * x) * rs - PBIAS);
                Sr[nb][e] = p;
                if (e < 2) l0 += p; else l1 += p;
            }

        // ---- pack P (plain fp16) ----
        uint32_t Pf[4][4];
#pragma unroll
        for (int kc = 0; kc < 4; ++kc) {
            Pf[kc][0] = packh(Sr[2 * kc][0],     Sr[2 * kc][1]);
            Pf[kc][1] = packh(Sr[2 * kc][2],     Sr[2 * kc][3]);
            Pf[kc][2] = packh(Sr[2 * kc + 1][0], Sr[2 * kc + 1][1]);
            Pf[kc][3] = packh(Sr[2 * kc + 1][2], Sr[2 * kc + 1][3]);
        }

        if (j + 1 < NT) { CP_WAIT1(); } else { CP_WAIT0(); }
        __syncthreads();

        // ---- PV: O += P @ V (x4-paired trans loads) ----
#pragma unroll
        for (int kc = 0; kc < 4; ++kc) {
            const uint32_t va = vrow4 + (uint32_t)kc * 2304u;
#pragma unroll
            for (int nb = 0; nb < 8; nb += 2) {
                uint32_t vr4[4], vi4[4];
                ldsm_x4t(vr4, sb + VSM(0) + va + nb * 16);
                ldsm_x4t(vi4, sb + VSM(1) + va + nb * 16);
                mma_f16(Or[nb],     Pf[kc], vr4);     mma_f16(Oi[nb],     Pf[kc], vi4);
                mma_f16(Or[nb + 1], Pf[kc], vr4 + 2); mma_f16(Oi[nb + 1], Pf[kc], vi4 + 2);
            }
        }
        __syncthreads();

        if (j + 1 < NT) { issueV(j + 1); CP_COMMIT(); }
    }

    // ---- epilogue ----
    l0 += __shfl_xor_sync(0xffffffffu, l0, 1);
    l0 += __shfl_xor_sync(0xffffffffu, l0, 2);
    l1 += __shfl_xor_sync(0xffffffffu, l1, 1);
    l1 += __shfl_xor_sync(0xffffffffu, l1, 2);
    const float inv0 = 1.f / l0, inv1 = 1.f / l1;
    const int b  = bh >> 4;
    const int hh = bh & 15;
    const int r0 = qt * 64 + w * 16 + (L >> 2);
    const size_t base0 = ((size_t)b * SEQ + r0) * DIM + hh * 64;
    const size_t base1 = base0 + (size_t)8 * DIM;
#pragma unroll
    for (int nb = 0; nb < 8; ++nb) {
        const int col = nb * 8 + 2 * (L & 3);
        *(uint32_t*)&g_oarh[base0 + col] = packh(Or[nb][0] * inv0, Or[nb][1] * inv0);
        *(uint32_t*)&g_oaih[base0 + col] = packh(Oi[nb][0] * inv0, Oi[nb][1] * inv0);
        *(uint32_t*)&g_oarh[base1 + col] = packh(Or[nb][2] * inv1, Or[nb][3] * inv1);
        *(uint32_t*)&g_oaih[base1 + col] = packh(Oi[nb][2] * inv1, Oi[nb][3] * inv1);
    }
}

// ============================================================
extern "C" void kernel_launch(void* const* d_in, const int* in_sizes, int n_in,
                              void* d_out, int out_size)
{
    const float* x_r    = (const float*)d_in[0];
    const float* x_i    = (const float*)d_in[1];
    const float* Wqkv_r = (const float*)d_in[2];
    const float* bqkv_r = (const float*)d_in[3];
    const float* Wqkv_i = (const float*)d_in[4];
    const float* bqkv_i = (const float*)d_in[5];
    const float* Wout_r = (const float*)d_in[6];
    const float* bout_r = (const float*)d_in[7];
    const float* Wout_i = (const float*)d_in[8];
    const float* bout_i = (const float*)d_in[9];

    cudaFuncSetAttribute(gemm_f16<1>, cudaFuncAttributeMaxDynamicSharedMemorySize, GEMM_SMEM);
    cudaFuncSetAttribute(gemm_f16<0>, cudaFuncAttributeMaxDynamicSharedMemorySize, GEMM_SMEM);
    cudaFuncSetAttribute(attn_mma,    cudaFuncAttributeMaxDynamicSharedMemorySize, ATT_SMEM);

    // 1) fused conversions
    split_all<<<2048, 256>>>(x_r, x_i, Wqkv_r, Wqkv_i, Wout_r, Wout_i);

    // 2) QKV projections (real + imag in one launch)
    dim3 gq(QKV_N / 128, M_TOTAL / 128, 2);    // (24, 32, 2)
    gemm_f16<1><<<gq, 256, GEMM_SMEM>>>(bqkv_r, bqkv_i, nullptr, nullptr);

    // 3) HMMA flash complex attention
    dim3 ga(SEQ / 64, BH);                     // (32, 32)
    attn_mma<<<ga, 128, ATT_SMEM>>>();

    // 4) output projections (real + imag in one launch)
    float* outr = (float*)d_out;
    float* outi = outr + (size_t)OUT_ELEMS;
    dim3 go(DIM / 128, M_TOTAL / 128, 2);      // (8, 32, 2)
    gemm_f16<0><<<go, 256, GEMM_SMEM>>>(bout_r, bout_i, outr, outi);
}